// round 1
// baseline (speedup 1.0000x reference)
#include <cuda_runtime.h>
#include <cuda_bf16.h>
#include <cstdint>

#define D 128
#define BM 64          // edges per CTA
#define BK 32          // K chunk
#define TM 4           // rows per thread
#define TN 8           // cols per thread
#define AS_STRIDE 388  // 384 + pad (4*388 % 32 = 16 -> conflict-free, %4==0 for float4)
#define HS_STRIDE 132  // 128 + pad

// scratch for per-graph sums (G=256 max, D=128)
__device__ float g_summed_nodes[256 * D];
__device__ float g_summed_edges[256 * D];

__device__ __forceinline__ float leaky(float x) {
    return x > 0.0f ? x : 0.01f * x;
}

// ---------------------------------------------------------------------------
// Fused edge kernel: gather concat[64,384] -> (msg MLP -> atomic scatter) and
// (edge MLP -> new_edges). Both 2-layer MLPs fused through smem hidden buffer.
// ---------------------------------------------------------------------------
__global__ __launch_bounds__(256, 1)
void edge_mlp_kernel(const float* __restrict__ nodes,
                     const float* __restrict__ edges,
                     const int*   __restrict__ senders,
                     const int*   __restrict__ receivers,
                     const float* __restrict__ nW0, const float* __restrict__ nb0,
                     const float* __restrict__ nW1, const float* __restrict__ nb1,
                     const float* __restrict__ eW0, const float* __restrict__ eb0,
                     const float* __restrict__ eW1, const float* __restrict__ eb1,
                     float* __restrict__ new_nodes,
                     float* __restrict__ new_edges,
                     int E)
{
    extern __shared__ float sm[];
    float* As = sm;                          // 64 * 388
    float* Ws = As + BM * AS_STRIDE;         // 32 * 128
    float* Hs = Ws + BK * D;                 // 64 * 132
    int*   sidx = (int*)(Hs + BM * HS_STRIDE);
    int*   ridx = sidx + BM;

    const int tid = threadIdx.x;
    const int tx = tid & 15;       // col group (x8)
    const int ty = tid >> 4;       // row group (x4)
    const int e0 = blockIdx.x * BM;

    if (tid < BM) {
        int e  = e0 + tid;
        int ec = (e < E) ? e : 0;
        sidx[tid] = senders[ec];
        ridx[tid] = receivers[ec];
    }
    __syncthreads();

    // gather concat rows: [sender | receiver | edge], 96 float4 per row
    for (int i = tid; i < BM * 96; i += 256) {
        int row = i / 96;
        int c4  = i - row * 96;
        int e   = e0 + row;
        int ec  = (e < E) ? e : 0;
        const float4* src;
        if (c4 < 32)       src = (const float4*)(nodes + (size_t)sidx[row] * D) + c4;
        else if (c4 < 64)  src = (const float4*)(nodes + (size_t)ridx[row] * D) + (c4 - 32);
        else               src = (const float4*)(edges + (size_t)ec * D) + (c4 - 64);
        *(float4*)(As + row * AS_STRIDE + c4 * 4) = *src;
    }
    __syncthreads();

    #pragma unroll 1
    for (int branch = 0; branch < 2; branch++) {
        const float* W0 = branch ? eW0 : nW0;
        const float* b0 = branch ? eb0 : nb0;
        const float* W1 = branch ? eW1 : nW1;
        const float* b1 = branch ? eb1 : nb1;

        float bias0[TN], bias1[TN];
        #pragma unroll
        for (int j = 0; j < TN; j++) {
            bias0[j] = __ldg(b0 + tx * TN + j);
            bias1[j] = __ldg(b1 + tx * TN + j);
        }

        float acc[TM][TN];
        #pragma unroll
        for (int i = 0; i < TM; i++)
            #pragma unroll
            for (int j = 0; j < TN; j++) acc[i][j] = 0.0f;

        // ---- layer 1: [64,384] @ [384,128] ----
        for (int kc = 0; kc < 3 * D; kc += BK) {
            const float4* wsrc = (const float4*)(W0 + (size_t)kc * D);
            float4* wdst = (float4*)Ws;
            #pragma unroll
            for (int p = 0; p < 4; p++) wdst[tid + p * 256] = wsrc[tid + p * 256];
            __syncthreads();

            #pragma unroll
            for (int kk = 0; kk < BK; kk++) {
                float a[TM];
                #pragma unroll
                for (int i = 0; i < TM; i++)
                    a[i] = As[(ty * TM + i) * AS_STRIDE + kc + kk];
                float4 w0 = *(const float4*)(Ws + kk * D + tx * TN);
                float4 w1 = *(const float4*)(Ws + kk * D + tx * TN + 4);
                float b[TN] = {w0.x, w0.y, w0.z, w0.w, w1.x, w1.y, w1.z, w1.w};
                #pragma unroll
                for (int i = 0; i < TM; i++)
                    #pragma unroll
                    for (int j = 0; j < TN; j++)
                        acc[i][j] = fmaf(a[i], b[j], acc[i][j]);
            }
            __syncthreads();
        }

        // bias + leaky -> Hs
        #pragma unroll
        for (int i = 0; i < TM; i++) {
            int row = ty * TM + i;
            #pragma unroll
            for (int j = 0; j < TN; j++)
                Hs[row * HS_STRIDE + tx * TN + j] = leaky(acc[i][j] + bias0[j]);
        }
        __syncthreads();

        // ---- layer 2: [64,128] @ [128,128] ----
        #pragma unroll
        for (int i = 0; i < TM; i++)
            #pragma unroll
            for (int j = 0; j < TN; j++) acc[i][j] = 0.0f;

        for (int kc = 0; kc < D; kc += BK) {
            const float4* wsrc = (const float4*)(W1 + (size_t)kc * D);
            float4* wdst = (float4*)Ws;
            #pragma unroll
            for (int p = 0; p < 4; p++) wdst[tid + p * 256] = wsrc[tid + p * 256];
            __syncthreads();

            #pragma unroll
            for (int kk = 0; kk < BK; kk++) {
                float a[TM];
                #pragma unroll
                for (int i = 0; i < TM; i++)
                    a[i] = Hs[(ty * TM + i) * HS_STRIDE + kc + kk];
                float4 w0 = *(const float4*)(Ws + kk * D + tx * TN);
                float4 w1 = *(const float4*)(Ws + kk * D + tx * TN + 4);
                float b[TN] = {w0.x, w0.y, w0.z, w0.w, w1.x, w1.y, w1.z, w1.w};
                #pragma unroll
                for (int i = 0; i < TM; i++)
                    #pragma unroll
                    for (int j = 0; j < TN; j++)
                        acc[i][j] = fmaf(a[i], b[j], acc[i][j]);
            }
            __syncthreads();
        }

        // bias + leaky + output
        if (branch == 0) {
            // message branch: scatter-add into new_nodes[receiver]
            #pragma unroll
            for (int i = 0; i < TM; i++) {
                int row = ty * TM + i;
                int e = e0 + row;
                if (e < E) {
                    float* dst = new_nodes + (size_t)ridx[row] * D + tx * TN;
                    #pragma unroll
                    for (int j = 0; j < TN; j++)
                        atomicAdd(dst + j, leaky(acc[i][j] + bias1[j]));
                }
            }
        } else {
            // edge branch: write new_edges
            #pragma unroll
            for (int i = 0; i < TM; i++) {
                int row = ty * TM + i;
                int e = e0 + row;
                if (e < E) {
                    float out[TN];
                    #pragma unroll
                    for (int j = 0; j < TN; j++)
                        out[j] = leaky(acc[i][j] + bias1[j]);
                    float4* dst = (float4*)(new_edges + (size_t)e * D + tx * TN);
                    dst[0] = make_float4(out[0], out[1], out[2], out[3]);
                    dst[1] = make_float4(out[4], out[5], out[6], out[7]);
                }
            }
        }
        __syncthreads();
    }
}

// ---------------------------------------------------------------------------
// Per-graph contiguous-segment sums of nodes / edges -> scratch
// grid (G, 2), block 128
// ---------------------------------------------------------------------------
__global__ void graph_sum_kernel(const float* __restrict__ nodes,
                                 const float* __restrict__ edges,
                                 const int* __restrict__ n_node,
                                 const int* __restrict__ n_edge,
                                 int G)
{
    int g = blockIdx.x;
    const float* src  = blockIdx.y ? edges : nodes;
    const int*   cnts = blockIdx.y ? n_edge : n_node;
    float*       dst  = blockIdx.y ? g_summed_edges : g_summed_nodes;

    int start = 0;
    for (int i = 0; i < g; i++) start += cnts[i];
    int cnt = cnts[g];

    int d = threadIdx.x;
    float s = 0.0f;
    const float* p = src + (size_t)start * D + d;
    for (int i = 0; i < cnt; i++) s += p[(size_t)i * D];
    dst[g * D + d] = s;
}

// ---------------------------------------------------------------------------
// Global branch: three small 2-layer MLPs + final MLP. grid G, block 128.
// ---------------------------------------------------------------------------
__device__ __forceinline__ void mlp2_128(const float* __restrict__ in,
                                         float* __restrict__ tmp,
                                         float* __restrict__ out,
                                         const float* __restrict__ W0,
                                         const float* __restrict__ b0,
                                         const float* __restrict__ W1,
                                         const float* __restrict__ b1,
                                         int d)
{
    float s = 0.0f;
    #pragma unroll 8
    for (int k = 0; k < D; k++) s = fmaf(in[k], __ldg(W0 + k * D + d), s);
    tmp[d] = leaky(s + __ldg(b0 + d));
    __syncthreads();
    float s2 = 0.0f;
    #pragma unroll 8
    for (int k = 0; k < D; k++) s2 = fmaf(tmp[k], __ldg(W1 + k * D + d), s2);
    out[d] = leaky(s2 + __ldg(b1 + d));
    __syncthreads();
}

__global__ void global_mlp_kernel(const float* __restrict__ globals_,
                                  const float* __restrict__ gW0, const float* __restrict__ gb0,
                                  const float* __restrict__ gW1, const float* __restrict__ gb1,
                                  const float* __restrict__ nW0, const float* __restrict__ nb0,
                                  const float* __restrict__ nW1, const float* __restrict__ nb1,
                                  const float* __restrict__ eW0, const float* __restrict__ eb0,
                                  const float* __restrict__ eW1, const float* __restrict__ eb1,
                                  const float* __restrict__ fW0, const float* __restrict__ fb0,
                                  const float* __restrict__ fW1, const float* __restrict__ fb1,
                                  float* __restrict__ out_global)
{
    __shared__ float x[D];
    __shared__ float h[D];
    __shared__ float cat[3 * D];
    int g = blockIdx.x;
    int d = threadIdx.x;

    x[d] = globals_[(size_t)g * D + d];
    __syncthreads();
    mlp2_128(x, h, cat, gW0, gb0, gW1, gb1, d);

    x[d] = g_summed_nodes[g * D + d];
    __syncthreads();
    mlp2_128(x, h, cat + D, nW0, nb0, nW1, nb1, d);

    x[d] = g_summed_edges[g * D + d];
    __syncthreads();
    mlp2_128(x, h, cat + 2 * D, eW0, eb0, eW1, eb1, d);

    // final MLP: 384 -> 128 -> 128
    float s = 0.0f;
    #pragma unroll 8
    for (int k = 0; k < 3 * D; k++) s = fmaf(cat[k], __ldg(fW0 + k * D + d), s);
    h[d] = leaky(s + __ldg(fb0 + d));
    __syncthreads();
    float s2 = 0.0f;
    #pragma unroll 8
    for (int k = 0; k < D; k++) s2 = fmaf(h[k], __ldg(fW1 + k * D + d), s2);
    out_global[(size_t)g * D + d] = leaky(s2 + __ldg(fb1 + d));
}

// ---------------------------------------------------------------------------
extern "C" void kernel_launch(void* const* d_in, const int* in_sizes, int n_in,
                              void* d_out, int out_size)
{
    const float* nodes    = (const float*)d_in[0];
    const float* edges    = (const float*)d_in[1];
    const float* globals_ = (const float*)d_in[2];
    const int*   senders   = (const int*)d_in[3];
    const int*   receivers = (const int*)d_in[4];
    const int*   n_node    = (const int*)d_in[5];
    const int*   n_edge    = (const int*)d_in[6];

    const float* node_W0 = (const float*)d_in[7];
    const float* node_b0 = (const float*)d_in[8];
    const float* node_W1 = (const float*)d_in[9];
    const float* node_b1 = (const float*)d_in[10];
    const float* edge_W0 = (const float*)d_in[11];
    const float* edge_b0 = (const float*)d_in[12];
    const float* edge_W1 = (const float*)d_in[13];
    const float* edge_b1 = (const float*)d_in[14];
    const float* glob_W0 = (const float*)d_in[15];
    const float* glob_b0 = (const float*)d_in[16];
    const float* glob_W1 = (const float*)d_in[17];
    const float* glob_b1 = (const float*)d_in[18];
    const float* gnode_W0 = (const float*)d_in[19];
    const float* gnode_b0 = (const float*)d_in[20];
    const float* gnode_W1 = (const float*)d_in[21];
    const float* gnode_b1 = (const float*)d_in[22];
    const float* gedge_W0 = (const float*)d_in[23];
    const float* gedge_b0 = (const float*)d_in[24];
    const float* gedge_W1 = (const float*)d_in[25];
    const float* gedge_b1 = (const float*)d_in[26];
    const float* fin_W0 = (const float*)d_in[27];
    const float* fin_b0 = (const float*)d_in[28];
    const float* fin_W1 = (const float*)d_in[29];
    const float* fin_b1 = (const float*)d_in[30];

    const int N = in_sizes[0] / D;
    const int E = in_sizes[3];
    const int G = in_sizes[5];

    float* new_nodes  = (float*)d_out;
    float* new_edges  = new_nodes + (size_t)N * D;
    float* new_global = new_edges + (size_t)E * D;

    // dynamic smem for the fused edge kernel
    const int smem_bytes = (BM * AS_STRIDE + BK * D + BM * HS_STRIDE) * 4 + 2 * BM * 4;
    cudaFuncSetAttribute(edge_mlp_kernel,
                         cudaFuncAttributeMaxDynamicSharedMemorySize, smem_bytes);

    // zero the segment-sum target (part of the captured graph)
    cudaMemsetAsync(new_nodes, 0, (size_t)N * D * sizeof(float), 0);

    // main fused edge kernel
    int grid = (E + BM - 1) / BM;
    edge_mlp_kernel<<<grid, 256, smem_bytes>>>(
        nodes, edges, senders, receivers,
        node_W0, node_b0, node_W1, node_b1,
        edge_W0, edge_b0, edge_W1, edge_b1,
        new_nodes, new_edges, E);

    // per-graph sums
    dim3 gs(G, 2);
    graph_sum_kernel<<<gs, D>>>(nodes, edges, n_node, n_edge, G);

    // global MLPs
    global_mlp_kernel<<<G, D>>>(globals_,
        glob_W0, glob_b0, glob_W1, glob_b1,
        gnode_W0, gnode_b0, gnode_W1, gnode_b1,
        gedge_W0, gedge_b0, gedge_W1, gedge_b1,
        fin_W0, fin_b0, fin_W1, fin_b1,
        new_global);
}

// round 3
// speedup vs baseline: 3.8815x; 3.8815x over previous
#include <cuda_runtime.h>
#include <cuda_bf16.h>
#include <cstdint>

#define D 128
#define TILE_B 18432            // one [128 rows][64 bf16 cols] tile, 144B stride
#define ROWSTRIDE 144
#define NTILES 12
#define TILES_BYTES (NTILES * TILE_B)      // 221184
#define IDX_OFF  TILES_BYTES               // sidx[128], ridx[128]
#define BIAS_OFF (IDX_OFF + 1024)          // 512 floats
#define SMEM_BYTES (BIAS_OFF + 2048)       // 224256
#define STAG_STRIDE 528                    // node-out staging row stride (16B aligned)

__device__ __forceinline__ uint32_t smem_u32(const void* p) {
    uint32_t a;
    asm("{ .reg .u64 t; cvta.to.shared.u64 t, %1; cvt.u32.u64 %0, t; }" : "=r"(a) : "l"(p));
    return a;
}
__device__ __forceinline__ float leaky(float x) { return x > 0.0f ? x : 0.01f * x; }
__device__ __forceinline__ uint32_t pack_bf16(float a, float b) {
    __nv_bfloat162 t = __floats2bfloat162_rn(a, b);
    return reinterpret_cast<uint32_t&>(t);
}
__device__ __forceinline__ void ldsm_x4(uint32_t addr, uint32_t r[4]) {
    asm volatile("ldmatrix.sync.aligned.m8n8.x4.shared.b16 {%0,%1,%2,%3}, [%4];"
                 : "=r"(r[0]), "=r"(r[1]), "=r"(r[2]), "=r"(r[3]) : "r"(addr));
}
__device__ __forceinline__ void mma_bf16(float* c, const uint32_t* a, uint32_t b0, uint32_t b1) {
    asm volatile("mma.sync.aligned.m16n8k16.row.col.f32.bf16.bf16.f32 "
                 "{%0,%1,%2,%3}, {%4,%5,%6,%7}, {%8,%9}, {%0,%1,%2,%3};"
                 : "+f"(c[0]), "+f"(c[1]), "+f"(c[2]), "+f"(c[3])
                 : "r"(a[0]), "r"(a[1]), "r"(a[2]), "r"(a[3]), "r"(b0), "r"(b1));
}
__device__ __forceinline__ void cp_async16(uint32_t saddr, const void* gaddr) {
    asm volatile("cp.async.cg.shared.global [%0], [%1], 16;" :: "r"(saddr), "l"(gaddr));
}
#define CP_COMMIT()  asm volatile("cp.async.commit_group;" ::: "memory")
#define CP_WAIT0()   asm volatile("cp.async.wait_group 0;" ::: "memory")
#define FENCE_PROXY_ASYNC() asm volatile("fence.proxy.async.shared::cta;" ::: "memory")

// ============================================================================
// Device scratch: split/transposed weights + per-graph sums
// ============================================================================
__device__ __nv_bfloat16 g_W0T_hi[2][128 * 384];  // [branch][n][k]
__device__ __nv_bfloat16 g_W0T_lo[2][128 * 384];
__device__ __nv_bfloat16 g_W1T_hi[2][128 * 128];
__device__ __nv_bfloat16 g_W1T_lo[2][128 * 128];
__device__ float g_summed_nodes[256 * 128];
__device__ float g_summed_edges[256 * 128];

__global__ void prep_weights(const float* __restrict__ nW0, const float* __restrict__ nW1,
                             const float* __restrict__ eW0, const float* __restrict__ eW1)
{
    int i = blockIdx.x * 256 + threadIdx.x;
    if (i < 98304) {                      // W0T: 2 * 128*384
        int b = i / 49152, r = i % 49152;
        int n = r / 384, k = r % 384;
        float v = (b ? eW0 : nW0)[k * 128 + n];
        __nv_bfloat16 h = __float2bfloat16(v);
        g_W0T_hi[b][n * 384 + k] = h;
        g_W0T_lo[b][n * 384 + k] = __float2bfloat16(v - __bfloat162float(h));
    } else if (i < 131072) {              // W1T: 2 * 128*128
        int j = i - 98304;
        int b = j / 16384, r = j % 16384;
        int n = r / 128, k = r % 128;
        float v = (b ? eW1 : nW1)[k * 128 + n];
        __nv_bfloat16 h = __float2bfloat16(v);
        g_W1T_hi[b][n * 128 + k] = h;
        g_W1T_lo[b][n * 128 + k] = __float2bfloat16(v - __bfloat162float(h));
    }
}

// ============================================================================
// Main fused edge kernel: mma.sync bf16 3-pass split
// Tiles: layer1 stage s (s=0,1): s*6 + {0:Ahi,1:Alo,2:Wn_hi,3:Wn_lo,4:We_hi,5:We_lo}
// Layer2: H: b0c0->0,1  b0c1->2,3  b1c0->6,7  b1c1->8,9 ; W1: c0->4,5  c1->10,11
// ============================================================================
__global__ __launch_bounds__(256, 1)
void edge_mma_kernel(const float* __restrict__ nodes,
                     const float* __restrict__ edges,
                     const int*   __restrict__ senders,
                     const int*   __restrict__ receivers,
                     const float* __restrict__ nb0f, const float* __restrict__ nb1f,
                     const float* __restrict__ eb0f, const float* __restrict__ eb1f,
                     float* __restrict__ new_nodes,
                     float* __restrict__ new_edges,
                     int E)
{
    extern __shared__ char smem[];
    const uint32_t sb = smem_u32(smem);
    const int tid  = threadIdx.x;
    const int wid  = tid >> 5;
    const int lane = tid & 31;
    const int wm   = wid >> 2;        // 0..1  (M offset wm*64)
    const int wn   = wid & 3;         // 0..3  (N offset wn*32)
    const int e0   = blockIdx.x * 128;

    int*   sidx = (int*)(smem + IDX_OFF);
    int*   ridx = (int*)(smem + IDX_OFF + 512);
    float* bias = (float*)(smem + BIAS_OFF);

    if (tid < 128) {
        int e  = e0 + tid;
        int ec = e < E ? e : E - 1;
        sidx[tid] = senders[ec];
        ridx[tid] = receivers[ec];
        bias[tid]       = nb0f[tid];
        bias[128 + tid] = nb1f[tid];
        bias[256 + tid] = eb0f[tid];
        bias[384 + tid] = eb1f[tid];
    }
    __syncthreads();

    float acc[2][4][4][4];
    #pragma unroll
    for (int b = 0; b < 2; b++)
        #pragma unroll
        for (int i = 0; i < 4; i++)
            #pragma unroll
            for (int j = 0; j < 4; j++)
                #pragma unroll
                for (int q = 0; q < 4; q++) acc[b][i][j][q] = 0.0f;

    // ---------------- helpers as lambdas ----------------
    auto fetchA = [&](int kc, float4 pf[8]) {
        int row = tid >> 1;
        const float* bp;
        int sec = kc >> 1;
        if (sec == 0)      bp = nodes + (size_t)sidx[row] * D;
        else if (sec == 1) bp = nodes + (size_t)ridx[row] * D;
        else { int e = e0 + row; int ec = e < E ? e : E - 1; bp = edges + (size_t)ec * D; }
        bp += (kc & 1) * 64;
        const float4* p4 = (const float4*)bp + (tid & 1) * 8;
        #pragma unroll
        for (int i = 0; i < 8; i++) pf[i] = p4[i];
    };
    auto storeA = [&](int stage, const float4 pf[8]) {
        int row = tid >> 1;
        char* Ah = smem + (stage * 6 + 0) * TILE_B;
        char* Al = smem + (stage * 6 + 1) * TILE_B;
        #pragma unroll
        for (int i = 0; i < 8; i++) {
            float4 x = pf[i];
            uint32_t h0 = pack_bf16(x.x, x.y);
            uint32_t h1 = pack_bf16(x.z, x.w);
            __nv_bfloat162 hh0 = reinterpret_cast<__nv_bfloat162&>(h0);
            __nv_bfloat162 hh1 = reinterpret_cast<__nv_bfloat162&>(h1);
            uint32_t l0 = pack_bf16(x.x - __low2float(hh0), x.y - __high2float(hh0));
            uint32_t l1 = pack_bf16(x.z - __low2float(hh1), x.w - __high2float(hh1));
            uint32_t off = row * ROWSTRIDE + ((tid & 1) * 8 + i) * 8;
            *(uint2*)(Ah + off) = make_uint2(h0, h1);
            *(uint2*)(Al + off) = make_uint2(l0, l1);
        }
    };
    auto cpasyncW0 = [&](int kc, int stage) {
        const char* gp[4] = {(const char*)g_W0T_hi[0], (const char*)g_W0T_lo[0],
                             (const char*)g_W0T_hi[1], (const char*)g_W0T_lo[1]};
        #pragma unroll
        for (int u = 0; u < 16; u++) {
            int i = tid + u * 256;
            int t = i >> 10, r = i & 1023, n = r >> 3, q = r & 7;
            cp_async16(sb + (stage * 6 + 2 + t) * TILE_B + n * ROWSTRIDE + q * 16,
                       gp[t] + n * 768 + kc * 128 + q * 16);
        }
    };
    auto cpasyncW1 = [&](int br) {
        const char* gp[2] = {(const char*)g_W1T_hi[br], (const char*)g_W1T_lo[br]};
        #pragma unroll
        for (int u = 0; u < 16; u++) {
            int i = tid + u * 256;
            int t = i >> 11, r = i & 2047, n = r >> 4, q = r & 15;
            int c = q >> 3, qq = q & 7;
            int tile = c == 0 ? (4 + t) : (10 + t);
            cp_async16(sb + tile * TILE_B + n * ROWSTRIDE + qq * 16,
                       gp[t] + n * 256 + q * 16);
        }
    };
    auto mma_2br = [&](int tA) {
        uint32_t Ah = sb + (tA + 0) * TILE_B, Al = sb + (tA + 1) * TILE_B;
        #pragma unroll
        for (int kk = 0; kk < 4; kk++) {
            uint32_t ah[4][4], al[4][4];
            #pragma unroll
            for (int i = 0; i < 4; i++) {
                uint32_t off = (wm * 64 + i * 16 + (lane & 15)) * ROWSTRIDE
                             + (lane >> 4) * 16 + kk * 32;
                ldsm_x4(Ah + off, ah[i]);
                ldsm_x4(Al + off, al[i]);
            }
            #pragma unroll
            for (int br = 0; br < 2; br++) {
                uint32_t Wh = sb + (tA + 2 + br * 2) * TILE_B;
                uint32_t Wl = Wh + TILE_B;
                uint32_t boffA = (wn * 32 + ((lane >> 4) * 8) + (lane & 7)) * ROWSTRIDE
                               + ((lane >> 3) & 1) * 16 + kk * 32;
                uint32_t boffB = boffA + 16 * ROWSTRIDE;
                uint32_t bh[2][4];
                ldsm_x4(Wh + boffA, bh[0]);
                ldsm_x4(Wh + boffB, bh[1]);
                #pragma unroll
                for (int i = 0; i < 4; i++)
                    #pragma unroll
                    for (int j = 0; j < 4; j++)
                        mma_bf16(acc[br][i][j], ah[i], bh[j >> 1][(j & 1) * 2], bh[j >> 1][(j & 1) * 2 + 1]);
                #pragma unroll
                for (int i = 0; i < 4; i++)
                    #pragma unroll
                    for (int j = 0; j < 4; j++)
                        mma_bf16(acc[br][i][j], al[i], bh[j >> 1][(j & 1) * 2], bh[j >> 1][(j & 1) * 2 + 1]);
                uint32_t bl[2][4];
                ldsm_x4(Wl + boffA, bl[0]);
                ldsm_x4(Wl + boffB, bl[1]);
                #pragma unroll
                for (int i = 0; i < 4; i++)
                    #pragma unroll
                    for (int j = 0; j < 4; j++)
                        mma_bf16(acc[br][i][j], ah[i], bl[j >> 1][(j & 1) * 2], bl[j >> 1][(j & 1) * 2 + 1]);
            }
        }
    };
    auto mma_1br = [&](int br, int tAh, int tAl, int tWh, int tWl) {
        uint32_t Ah = sb + tAh * TILE_B, Al = sb + tAl * TILE_B;
        uint32_t Wh = sb + tWh * TILE_B, Wl = sb + tWl * TILE_B;
        #pragma unroll
        for (int kk = 0; kk < 4; kk++) {
            uint32_t ah[4][4], al[4][4];
            #pragma unroll
            for (int i = 0; i < 4; i++) {
                uint32_t off = (wm * 64 + i * 16 + (lane & 15)) * ROWSTRIDE
                             + (lane >> 4) * 16 + kk * 32;
                ldsm_x4(Ah + off, ah[i]);
                ldsm_x4(Al + off, al[i]);
            }
            uint32_t boffA = (wn * 32 + ((lane >> 4) * 8) + (lane & 7)) * ROWSTRIDE
                           + ((lane >> 3) & 1) * 16 + kk * 32;
            uint32_t boffB = boffA + 16 * ROWSTRIDE;
            uint32_t bh[2][4];
            ldsm_x4(Wh + boffA, bh[0]);
            ldsm_x4(Wh + boffB, bh[1]);
            #pragma unroll
            for (int i = 0; i < 4; i++)
                #pragma unroll
                for (int j = 0; j < 4; j++)
                    mma_bf16(acc[br][i][j], ah[i], bh[j >> 1][(j & 1) * 2], bh[j >> 1][(j & 1) * 2 + 1]);
            #pragma unroll
            for (int i = 0; i < 4; i++)
                #pragma unroll
                for (int j = 0; j < 4; j++)
                    mma_bf16(acc[br][i][j], al[i], bh[j >> 1][(j & 1) * 2], bh[j >> 1][(j & 1) * 2 + 1]);
            uint32_t bl[2][4];
            ldsm_x4(Wl + boffA, bl[0]);
            ldsm_x4(Wl + boffB, bl[1]);
            #pragma unroll
            for (int i = 0; i < 4; i++)
                #pragma unroll
                for (int j = 0; j < 4; j++)
                    mma_bf16(acc[br][i][j], ah[i], bl[j >> 1][(j & 1) * 2], bl[j >> 1][(j & 1) * 2 + 1]);
        }
    };

    // ---------------- layer 1: 6 K-chunks, double-buffered ----------------
    {
        float4 pf[8];
        fetchA(0, pf);
        cpasyncW0(0, 0);
        CP_COMMIT();
        storeA(0, pf);
        CP_WAIT0();
        __syncthreads();

        #pragma unroll 1
        for (int kc = 0; kc < 6; kc++) {
            int stage = kc & 1;
            if (kc < 5) {
                fetchA(kc + 1, pf);
                cpasyncW0(kc + 1, stage ^ 1);
                CP_COMMIT();
            }
            mma_2br(stage * 6);
            if (kc < 5) {
                storeA(stage ^ 1, pf);
                CP_WAIT0();
            }
            __syncthreads();
        }
    }

    // ---------------- epilogue 1: H = split(leaky(acc + b0)); load W1 b0 ---
    cpasyncW1(0);
    CP_COMMIT();
    {
        const int chunk = wn >> 1;
        #pragma unroll
        for (int br = 0; br < 2; br++) {
            int th = br ? (chunk ? 8 : 6) : (chunk ? 2 : 0);
            char* Hh = smem + th * TILE_B;
            char* Hl = Hh + TILE_B;
            const float* b0p = bias + br * 256;
            #pragma unroll
            for (int i = 0; i < 4; i++) {
                int r0 = wm * 64 + i * 16 + (lane >> 2);
                #pragma unroll
                for (int j = 0; j < 4; j++) {
                    int c  = wn * 32 + j * 8 + (lane & 3) * 2;
                    int cl = c & 63;
                    float2 bb = *(const float2*)(b0p + c);
                    float v0 = leaky(acc[br][i][j][0] + bb.x);
                    float v1 = leaky(acc[br][i][j][1] + bb.y);
                    float v2 = leaky(acc[br][i][j][2] + bb.x);
                    float v3 = leaky(acc[br][i][j][3] + bb.y);
                    uint32_t h01 = pack_bf16(v0, v1);
                    uint32_t h23 = pack_bf16(v2, v3);
                    __nv_bfloat162 q01 = reinterpret_cast<__nv_bfloat162&>(h01);
                    __nv_bfloat162 q23 = reinterpret_cast<__nv_bfloat162&>(h23);
                    uint32_t l01 = pack_bf16(v0 - __low2float(q01), v1 - __high2float(q01));
                    uint32_t l23 = pack_bf16(v2 - __low2float(q23), v3 - __high2float(q23));
                    *(uint32_t*)(Hh + r0 * ROWSTRIDE + cl * 2) = h01;
                    *(uint32_t*)(Hl + r0 * ROWSTRIDE + cl * 2) = l01;
                    *(uint32_t*)(Hh + (r0 + 8) * ROWSTRIDE + cl * 2) = h23;
                    *(uint32_t*)(Hl + (r0 + 8) * ROWSTRIDE + cl * 2) = l23;
                }
            }
        }
    }
    CP_WAIT0();
    __syncthreads();

    // ---------------- layer 2 branch 0 (node messages) ---------------------
    #pragma unroll
    for (int i = 0; i < 4; i++)
        #pragma unroll
        for (int j = 0; j < 4; j++)
            #pragma unroll
            for (int q = 0; q < 4; q++) acc[0][i][j][q] = 0.0f;
    mma_1br(0, 0, 1, 4, 5);
    mma_1br(0, 2, 3, 10, 11);
    __syncthreads();

    // ---------------- stage node-out; load W1 b1; TMA-reduce scatter -------
    cpasyncW1(1);
    CP_COMMIT();
    {
        char* stag = smem;   // tiles 0-3: 128 rows x 528B
        const float* b1p = bias + 128;
        #pragma unroll
        for (int i = 0; i < 4; i++) {
            int r0 = wm * 64 + i * 16 + (lane >> 2);
            #pragma unroll
            for (int j = 0; j < 4; j++) {
                int c = wn * 32 + j * 8 + (lane & 3) * 2;
                float2 bb = *(const float2*)(b1p + c);
                *(float2*)(stag + r0 * STAG_STRIDE + c * 4) =
                    make_float2(leaky(acc[0][i][j][0] + bb.x), leaky(acc[0][i][j][1] + bb.y));
                *(float2*)(stag + (r0 + 8) * STAG_STRIDE + c * 4) =
                    make_float2(leaky(acc[0][i][j][2] + bb.x), leaky(acc[0][i][j][3] + bb.y));
            }
        }
    }
    CP_WAIT0();
    __syncthreads();
    FENCE_PROXY_ASYNC();
    if (tid < 128 && (e0 + tid) < E) {
        const float* dst = new_nodes + (size_t)ridx[tid] * D;
        asm volatile("cp.reduce.async.bulk.global.shared::cta.bulk_group.add.f32 [%0], [%1], %2;"
                     :: "l"(dst), "r"(sb + tid * STAG_STRIDE), "r"(512) : "memory");
    }
    asm volatile("cp.async.bulk.commit_group;" ::: "memory");

    // ---------------- layer 2 branch 1 (edge update) ------------------------
    #pragma unroll
    for (int i = 0; i < 4; i++)
        #pragma unroll
        for (int j = 0; j < 4; j++)
            #pragma unroll
            for (int q = 0; q < 4; q++) acc[1][i][j][q] = 0.0f;
    mma_1br(1, 6, 7, 4, 5);
    mma_1br(1, 8, 9, 10, 11);

    {
        const float* b1p = bias + 384;
        #pragma unroll
        for (int i = 0; i < 4; i++) {
            int r0 = wm * 64 + i * 16 + (lane >> 2);
            #pragma unroll
            for (int j = 0; j < 4; j++) {
                int c = wn * 32 + j * 8 + (lane & 3) * 2;
                float2 bb = *(const float2*)(b1p + c);
                int eA = e0 + r0, eB = eA + 8;
                if (eA < E)
                    *(float2*)(new_edges + (size_t)eA * D + c) =
                        make_float2(leaky(acc[1][i][j][0] + bb.x), leaky(acc[1][i][j][1] + bb.y));
                if (eB < E)
                    *(float2*)(new_edges + (size_t)eB * D + c) =
                        make_float2(leaky(acc[1][i][j][2] + bb.x), leaky(acc[1][i][j][3] + bb.y));
            }
        }
    }
    asm volatile("cp.async.bulk.wait_group.read 0;" ::: "memory");
}

// ============================================================================
// Per-graph segment sums -> scratch (atomics over PARTS)
// ============================================================================
#define PARTS 4
__global__ void graph_sum_kernel(const float* __restrict__ nodes,
                                 const float* __restrict__ edges,
                                 const int* __restrict__ n_node,
                                 const int* __restrict__ n_edge, int G)
{
    int g = blockIdx.x, which = blockIdx.y, part = blockIdx.z;
    const float* src = which ? edges : nodes;
    const int*  cnts = which ? n_edge : n_node;
    float*       dst = which ? g_summed_edges : g_summed_nodes;

    int start = 0;
    for (int i = 0; i < g; i++) start += cnts[i];
    int cnt = cnts[g];

    int d = threadIdx.x;
    float s = 0.0f;
    for (int i = part; i < cnt; i += PARTS)
        s += src[(size_t)(start + i) * D + d];
    atomicAdd(&dst[g * D + d], s);
}

// ============================================================================
// Global branch (tiny): 3 MLPs + final MLP
// ============================================================================
__device__ __forceinline__ void mlp2_128(const float* in, float* tmp, float* out,
                                         const float* W0, const float* b0,
                                         const float* W1, const float* b1, int d)
{
    float s = 0.0f;
    #pragma unroll 8
    for (int k = 0; k < D; k++) s = fmaf(in[k], __ldg(W0 + k * D + d), s);
    tmp[d] = leaky(s + __ldg(b0 + d));
    __syncthreads();
    float s2 = 0.0f;
    #pragma unroll 8
    for (int k = 0; k < D; k++) s2 = fmaf(tmp[k], __ldg(W1 + k * D + d), s2);
    out[d] = leaky(s2 + __ldg(b1 + d));
    __syncthreads();
}

__global__ void global_mlp_kernel(const float* __restrict__ globals_,
                                  const float* gW0, const float* gb0, const float* gW1, const float* gb1,
                                  const float* nW0, const float* nb0, const float* nW1, const float* nb1,
                                  const float* eW0, const float* eb0, const float* eW1, const float* eb1,
                                  const float* fW0, const float* fb0, const float* fW1, const float* fb1,
                                  float* __restrict__ out_global)
{
    __shared__ float x[D];
    __shared__ float h[D];
    __shared__ float cat[3 * D];
    int g = blockIdx.x, d = threadIdx.x;

    x[d] = globals_[(size_t)g * D + d];
    __syncthreads();
    mlp2_128(x, h, cat, gW0, gb0, gW1, gb1, d);

    x[d] = g_summed_nodes[g * D + d];
    __syncthreads();
    mlp2_128(x, h, cat + D, nW0, nb0, nW1, nb1, d);

    x[d] = g_summed_edges[g * D + d];
    __syncthreads();
    mlp2_128(x, h, cat + 2 * D, eW0, eb0, eW1, eb1, d);

    float s = 0.0f;
    #pragma unroll 8
    for (int k = 0; k < 3 * D; k++) s = fmaf(cat[k], __ldg(fW0 + k * D + d), s);
    h[d] = leaky(s + __ldg(fb0 + d));
    __syncthreads();
    float s2 = 0.0f;
    #pragma unroll 8
    for (int k = 0; k < D; k++) s2 = fmaf(h[k], __ldg(fW1 + k * D + d), s2);
    out_global[(size_t)g * D + d] = leaky(s2 + __ldg(fb1 + d));
}

// ============================================================================
extern "C" void kernel_launch(void* const* d_in, const int* in_sizes, int n_in,
                              void* d_out, int out_size)
{
    const float* nodes     = (const float*)d_in[0];
    const float* edges     = (const float*)d_in[1];
    const float* globals_  = (const float*)d_in[2];
    const int*   senders   = (const int*)d_in[3];
    const int*   receivers = (const int*)d_in[4];
    const int*   n_node    = (const int*)d_in[5];
    const int*   n_edge    = (const int*)d_in[6];

    const float* node_W0 = (const float*)d_in[7];
    const float* node_b0 = (const float*)d_in[8];
    const float* node_W1 = (const float*)d_in[9];
    const float* node_b1 = (const float*)d_in[10];
    const float* edge_W0 = (const float*)d_in[11];
    const float* edge_b0 = (const float*)d_in[12];
    const float* edge_W1 = (const float*)d_in[13];
    const float* edge_b1 = (const float*)d_in[14];
    const float* glob_W0 = (const float*)d_in[15];
    const float* glob_b0 = (const float*)d_in[16];
    const float* glob_W1 = (const float*)d_in[17];
    const float* glob_b1 = (const float*)d_in[18];
    const float* gnode_W0 = (const float*)d_in[19];
    const float* gnode_b0 = (const float*)d_in[20];
    const float* gnode_W1 = (const float*)d_in[21];
    const float* gnode_b1 = (const float*)d_in[22];
    const float* gedge_W0 = (const float*)d_in[23];
    const float* gedge_b0 = (const float*)d_in[24];
    const float* gedge_W1 = (const float*)d_in[25];
    const float* gedge_b1 = (const float*)d_in[26];
    const float* fin_W0 = (const float*)d_in[27];
    const float* fin_b0 = (const float*)d_in[28];
    const float* fin_W1 = (const float*)d_in[29];
    const float* fin_b1 = (const float*)d_in[30];

    const int N = in_sizes[0] / D;
    const int E = in_sizes[3];
    const int G = in_sizes[5];

    float* new_nodes  = (float*)d_out;
    float* new_edges  = new_nodes + (size_t)N * D;
    float* new_global = new_edges + (size_t)E * D;

    // zero targets (inside captured graph)
    cudaMemsetAsync(new_nodes, 0, (size_t)N * D * sizeof(float), 0);
    void *sp0, *sp1;
    cudaGetSymbolAddress(&sp0, g_summed_nodes);
    cudaGetSymbolAddress(&sp1, g_summed_edges);
    cudaMemsetAsync(sp0, 0, 256 * 128 * sizeof(float), 0);
    cudaMemsetAsync(sp1, 0, 256 * 128 * sizeof(float), 0);

    prep_weights<<<512, 256>>>(node_W0, node_W1, edge_W0, edge_W1);

    cudaFuncSetAttribute(edge_mma_kernel,
                         cudaFuncAttributeMaxDynamicSharedMemorySize, SMEM_BYTES);
    int grid = (E + 127) / 128;
    edge_mma_kernel<<<grid, 256, SMEM_BYTES>>>(
        nodes, edges, senders, receivers,
        node_b0, node_b1, edge_b0, edge_b1,
        new_nodes, new_edges, E);

    dim3 gs(G, 2, PARTS);
    graph_sum_kernel<<<gs, 128>>>(nodes, edges, n_node, n_edge, G);
    global_mlp_kernel<<<G, 128>>>(globals_,
        glob_W0, glob_b0, glob_W1, glob_b1,
        gnode_W0, gnode_b0, gnode_W1, gnode_b1,
        gedge_W0, gedge_b0, gedge_W1, gedge_b1,
        fin_W0, fin_b0, fin_W1, fin_b1,
        new_global);
}

// round 4
// speedup vs baseline: 4.0992x; 1.0561x over previous
#include <cuda_runtime.h>
#include <cuda_bf16.h>
#include <cstdint>

#define D 128
#define TILE_B 18432            // one [128 rows][64 bf16 cols] tile, 144B stride
#define ROWSTRIDE 144
#define NTILES 12
#define TILES_BYTES (NTILES * TILE_B)      // 221184
#define IDX_OFF  TILES_BYTES               // sidx[128], ridx[128]
#define BIAS_OFF (IDX_OFF + 1024)          // 512 floats
#define SMEM_BYTES (BIAS_OFF + 2048)       // 224256
#define STAG_STRIDE 528                    // node-out staging row stride (16B aligned)

__device__ __forceinline__ uint32_t smem_u32(const void* p) {
    uint32_t a;
    asm("{ .reg .u64 t; cvta.to.shared.u64 t, %1; cvt.u32.u64 %0, t; }" : "=r"(a) : "l"(p));
    return a;
}
__device__ __forceinline__ float leaky(float x) { return x > 0.0f ? x : 0.01f * x; }
__device__ __forceinline__ uint32_t pack_bf16(float a, float b) {
    __nv_bfloat162 t = __floats2bfloat162_rn(a, b);
    return reinterpret_cast<uint32_t&>(t);
}
__device__ __forceinline__ void ldsm_x4(uint32_t addr, uint32_t r[4]) {
    asm volatile("ldmatrix.sync.aligned.m8n8.x4.shared.b16 {%0,%1,%2,%3}, [%4];"
                 : "=r"(r[0]), "=r"(r[1]), "=r"(r[2]), "=r"(r[3]) : "r"(addr));
}
__device__ __forceinline__ void mma_bf16(float* c, const uint32_t* a, uint32_t b0, uint32_t b1) {
    asm volatile("mma.sync.aligned.m16n8k16.row.col.f32.bf16.bf16.f32 "
                 "{%0,%1,%2,%3}, {%4,%5,%6,%7}, {%8,%9}, {%0,%1,%2,%3};"
                 : "+f"(c[0]), "+f"(c[1]), "+f"(c[2]), "+f"(c[3])
                 : "r"(a[0]), "r"(a[1]), "r"(a[2]), "r"(a[3]), "r"(b0), "r"(b1));
}
__device__ __forceinline__ void cp_async16(uint32_t saddr, const void* gaddr) {
    asm volatile("cp.async.cg.shared.global [%0], [%1], 16;" :: "r"(saddr), "l"(gaddr));
}
#define CP_COMMIT()  asm volatile("cp.async.commit_group;" ::: "memory")
#define CP_WAIT0()   asm volatile("cp.async.wait_group 0;" ::: "memory")
#define FENCE_PROXY_ASYNC() asm volatile("fence.proxy.async.shared::cta;" ::: "memory")

// ============================================================================
// Device scratch
// ============================================================================
__device__ __nv_bfloat16 g_W0T_hi[2][128 * 384];  // [branch][n][k]
__device__ __nv_bfloat16 g_W0T_lo[2][128 * 384];
__device__ __nv_bfloat16 g_W1T_hi[2][128 * 128];
__device__ __nv_bfloat16 g_W1T_lo[2][128 * 128];
__device__ float g_part[2][256][4][128];          // per-graph partial sums
__device__ float g_cat[256][384];                 // concat of 3 global-branch MLPs

// ============================================================================
// [0] zero new_nodes
// ============================================================================
__global__ void zero_nodes_kernel(float4* __restrict__ p, int n4) {
    int i = blockIdx.x * 256 + threadIdx.x;
    if (i < n4) p[i] = make_float4(0.f, 0.f, 0.f, 0.f);
}

// ============================================================================
// [1] weight prep: transpose + bf16 hi/lo split
// ============================================================================
__global__ void prep_weights(const float* __restrict__ nW0, const float* __restrict__ nW1,
                             const float* __restrict__ eW0, const float* __restrict__ eW1)
{
    int i = blockIdx.x * 256 + threadIdx.x;
    if (i < 98304) {                      // W0T: 2 * 128*384
        int b = i / 49152, r = i % 49152;
        int n = r / 384, k = r % 384;
        float v = (b ? eW0 : nW0)[k * 128 + n];
        __nv_bfloat16 h = __float2bfloat16(v);
        g_W0T_hi[b][n * 384 + k] = h;
        g_W0T_lo[b][n * 384 + k] = __float2bfloat16(v - __bfloat162float(h));
    } else if (i < 131072) {              // W1T: 2 * 128*128
        int j = i - 98304;
        int b = j / 16384, r = j % 16384;
        int n = r / 128, k = r % 128;
        float v = (b ? eW1 : nW1)[k * 128 + n];
        __nv_bfloat16 h = __float2bfloat16(v);
        g_W1T_hi[b][n * 128 + k] = h;
        g_W1T_lo[b][n * 128 + k] = __float2bfloat16(v - __bfloat162float(h));
    }
}

// ============================================================================
// [2] per-graph segment partial sums (no atomics): grid (G, 2, 4), block 128
// ============================================================================
__global__ void graph_sum_kernel(const float* __restrict__ nodes,
                                 const float* __restrict__ edges,
                                 const int* __restrict__ n_node,
                                 const int* __restrict__ n_edge, int G)
{
    int g = blockIdx.x, which = blockIdx.y, part = blockIdx.z;
    const float* src = which ? edges : nodes;
    const int*  cnts = which ? n_edge : n_node;

    int start = 0;
    for (int i = 0; i < g; i++) start += cnts[i];
    int cnt = cnts[g];

    int d = threadIdx.x;
    float s0 = 0.f, s1 = 0.f, s2 = 0.f, s3 = 0.f;
    const float* p = src + (size_t)start * D + d;
    int i = part;
    for (; i + 3 * 4 < cnt; i += 16) {
        s0 += p[(size_t)i * D];
        s1 += p[(size_t)(i + 4) * D];
        s2 += p[(size_t)(i + 8) * D];
        s3 += p[(size_t)(i + 12) * D];
    }
    for (; i < cnt; i += 4) s0 += p[(size_t)i * D];
    g_part[which][g][part][d] = s0 + s1 + s2 + s3;
}

// ============================================================================
// [3] global branch MLPs: grid (G, 3), block 128 -> g_cat
// ============================================================================
__global__ void global_branch_kernel(const float* __restrict__ globals_,
                                     const float* gW0, const float* gb0, const float* gW1, const float* gb1,
                                     const float* nW0, const float* nb0, const float* nW1, const float* nb1,
                                     const float* eW0, const float* eb0, const float* eW1, const float* eb1)
{
    __shared__ float in[D];
    __shared__ float h[D];
    int g = blockIdx.x, b = blockIdx.y, d = threadIdx.x;

    const float *W0, *b0, *W1, *b1;
    if (b == 0)      { W0 = gW0; b0 = gb0; W1 = gW1; b1 = gb1;
                       in[d] = globals_[(size_t)g * D + d]; }
    else if (b == 1) { W0 = nW0; b0 = nb0; W1 = nW1; b1 = nb1;
                       in[d] = g_part[0][g][0][d] + g_part[0][g][1][d]
                             + g_part[0][g][2][d] + g_part[0][g][3][d]; }
    else             { W0 = eW0; b0 = eb0; W1 = eW1; b1 = eb1;
                       in[d] = g_part[1][g][0][d] + g_part[1][g][1][d]
                             + g_part[1][g][2][d] + g_part[1][g][3][d]; }
    __syncthreads();

    float a0 = 0.f, a1 = 0.f, a2 = 0.f, a3 = 0.f;
    #pragma unroll 8
    for (int k = 0; k < D; k += 4) {
        a0 = fmaf(in[k],     __ldg(W0 + k * D + d),       a0);
        a1 = fmaf(in[k + 1], __ldg(W0 + (k + 1) * D + d), a1);
        a2 = fmaf(in[k + 2], __ldg(W0 + (k + 2) * D + d), a2);
        a3 = fmaf(in[k + 3], __ldg(W0 + (k + 3) * D + d), a3);
    }
    h[d] = leaky((a0 + a1) + (a2 + a3) + __ldg(b0 + d));
    __syncthreads();

    a0 = a1 = a2 = a3 = 0.f;
    #pragma unroll 8
    for (int k = 0; k < D; k += 4) {
        a0 = fmaf(h[k],     __ldg(W1 + k * D + d),       a0);
        a1 = fmaf(h[k + 1], __ldg(W1 + (k + 1) * D + d), a1);
        a2 = fmaf(h[k + 2], __ldg(W1 + (k + 2) * D + d), a2);
        a3 = fmaf(h[k + 3], __ldg(W1 + (k + 3) * D + d), a3);
    }
    g_cat[g][b * D + d] = leaky((a0 + a1) + (a2 + a3) + __ldg(b1 + d));
}

// ============================================================================
// [4] final global MLP: grid G, block 128
// ============================================================================
__global__ void global_final_kernel(const float* fW0, const float* fb0,
                                    const float* fW1, const float* fb1,
                                    float* __restrict__ out_global)
{
    __shared__ float cat[3 * D];
    __shared__ float h[D];
    int g = blockIdx.x, d = threadIdx.x;
    cat[d]         = g_cat[g][d];
    cat[D + d]     = g_cat[g][D + d];
    cat[2 * D + d] = g_cat[g][2 * D + d];
    __syncthreads();

    float a0 = 0.f, a1 = 0.f, a2 = 0.f, a3 = 0.f;
    #pragma unroll 8
    for (int k = 0; k < 3 * D; k += 4) {
        a0 = fmaf(cat[k],     __ldg(fW0 + k * D + d),       a0);
        a1 = fmaf(cat[k + 1], __ldg(fW0 + (k + 1) * D + d), a1);
        a2 = fmaf(cat[k + 2], __ldg(fW0 + (k + 2) * D + d), a2);
        a3 = fmaf(cat[k + 3], __ldg(fW0 + (k + 3) * D + d), a3);
    }
    h[d] = leaky((a0 + a1) + (a2 + a3) + __ldg(fb0 + d));
    __syncthreads();

    a0 = a1 = a2 = a3 = 0.f;
    #pragma unroll 8
    for (int k = 0; k < D; k += 4) {
        a0 = fmaf(h[k],     __ldg(fW1 + k * D + d),       a0);
        a1 = fmaf(h[k + 1], __ldg(fW1 + (k + 1) * D + d), a1);
        a2 = fmaf(h[k + 2], __ldg(fW1 + (k + 2) * D + d), a2);
        a3 = fmaf(h[k + 3], __ldg(fW1 + (k + 3) * D + d), a3);
    }
    out_global[(size_t)g * D + d] = leaky((a0 + a1) + (a2 + a3) + __ldg(fb1 + d));
}

// ============================================================================
// [5] main fused edge kernel: mma.sync bf16 3-pass split
// ============================================================================
__global__ __launch_bounds__(256, 1)
void edge_mma_kernel(const float* __restrict__ nodes,
                     const float* __restrict__ edges,
                     const int*   __restrict__ senders,
                     const int*   __restrict__ receivers,
                     const float* __restrict__ nb0f, const float* __restrict__ nb1f,
                     const float* __restrict__ eb0f, const float* __restrict__ eb1f,
                     float* __restrict__ new_nodes,
                     float* __restrict__ new_edges,
                     int E)
{
    extern __shared__ char smem[];
    const uint32_t sb = smem_u32(smem);
    const int tid  = threadIdx.x;
    const int wid  = tid >> 5;
    const int lane = tid & 31;
    const int wm   = wid >> 2;        // 0..1  (M offset wm*64)
    const int wn   = wid & 3;         // 0..3  (N offset wn*32)
    const int e0   = blockIdx.x * 128;

    int*   sidx = (int*)(smem + IDX_OFF);
    int*   ridx = (int*)(smem + IDX_OFF + 512);
    float* bias = (float*)(smem + BIAS_OFF);

    if (tid < 128) {
        int e  = e0 + tid;
        int ec = e < E ? e : E - 1;
        sidx[tid] = senders[ec];
        ridx[tid] = receivers[ec];
        bias[tid]       = nb0f[tid];
        bias[128 + tid] = nb1f[tid];
        bias[256 + tid] = eb0f[tid];
        bias[384 + tid] = eb1f[tid];
    }
    __syncthreads();

    float acc[2][4][4][4];
    #pragma unroll
    for (int b = 0; b < 2; b++)
        #pragma unroll
        for (int i = 0; i < 4; i++)
            #pragma unroll
            for (int j = 0; j < 4; j++)
                #pragma unroll
                for (int q = 0; q < 4; q++) acc[b][i][j][q] = 0.0f;

    auto fetchA = [&](int kc, float4 pf[8]) {
        int row = tid >> 1;
        const float* bp;
        int sec = kc >> 1;
        if (sec == 0)      bp = nodes + (size_t)sidx[row] * D;
        else if (sec == 1) bp = nodes + (size_t)ridx[row] * D;
        else { int e = e0 + row; int ec = e < E ? e : E - 1; bp = edges + (size_t)ec * D; }
        bp += (kc & 1) * 64;
        const float4* p4 = (const float4*)bp + (tid & 1) * 8;
        #pragma unroll
        for (int i = 0; i < 8; i++) pf[i] = p4[i];
    };
    auto storeA = [&](int stage, const float4 pf[8]) {
        int row = tid >> 1;
        char* Ah = smem + (stage * 6 + 0) * TILE_B;
        char* Al = smem + (stage * 6 + 1) * TILE_B;
        #pragma unroll
        for (int i = 0; i < 8; i++) {
            float4 x = pf[i];
            uint32_t h0 = pack_bf16(x.x, x.y);
            uint32_t h1 = pack_bf16(x.z, x.w);
            __nv_bfloat162 hh0 = reinterpret_cast<__nv_bfloat162&>(h0);
            __nv_bfloat162 hh1 = reinterpret_cast<__nv_bfloat162&>(h1);
            uint32_t l0 = pack_bf16(x.x - __low2float(hh0), x.y - __high2float(hh0));
            uint32_t l1 = pack_bf16(x.z - __low2float(hh1), x.w - __high2float(hh1));
            uint32_t off = row * ROWSTRIDE + ((tid & 1) * 8 + i) * 8;
            *(uint2*)(Ah + off) = make_uint2(h0, h1);
            *(uint2*)(Al + off) = make_uint2(l0, l1);
        }
    };
    auto cpasyncW0 = [&](int kc, int stage) {
        const char* gp[4] = {(const char*)g_W0T_hi[0], (const char*)g_W0T_lo[0],
                             (const char*)g_W0T_hi[1], (const char*)g_W0T_lo[1]};
        #pragma unroll
        for (int u = 0; u < 16; u++) {
            int i = tid + u * 256;
            int t = i >> 10, r = i & 1023, n = r >> 3, q = r & 7;
            cp_async16(sb + (stage * 6 + 2 + t) * TILE_B + n * ROWSTRIDE + q * 16,
                       gp[t] + n * 768 + kc * 128 + q * 16);
        }
    };
    auto cpasyncW1 = [&](int br) {
        const char* gp[2] = {(const char*)g_W1T_hi[br], (const char*)g_W1T_lo[br]};
        #pragma unroll
        for (int u = 0; u < 16; u++) {
            int i = tid + u * 256;
            int t = i >> 11, r = i & 2047, n = r >> 4, q = r & 15;
            int c = q >> 3, qq = q & 7;
            int tile = c == 0 ? (4 + t) : (10 + t);
            cp_async16(sb + tile * TILE_B + n * ROWSTRIDE + qq * 16,
                       gp[t] + n * 256 + q * 16);
        }
    };
    auto mma_2br = [&](int tA) {
        uint32_t Ah = sb + (tA + 0) * TILE_B, Al = sb + (tA + 1) * TILE_B;
        #pragma unroll
        for (int kk = 0; kk < 4; kk++) {
            uint32_t ah[4][4], al[4][4];
            #pragma unroll
            for (int i = 0; i < 4; i++) {
                uint32_t off = (wm * 64 + i * 16 + (lane & 15)) * ROWSTRIDE
                             + (lane >> 4) * 16 + kk * 32;
                ldsm_x4(Ah + off, ah[i]);
                ldsm_x4(Al + off, al[i]);
            }
            #pragma unroll
            for (int br = 0; br < 2; br++) {
                uint32_t Wh = sb + (tA + 2 + br * 2) * TILE_B;
                uint32_t Wl = Wh + TILE_B;
                uint32_t boffA = (wn * 32 + ((lane >> 4) * 8) + (lane & 7)) * ROWSTRIDE
                               + ((lane >> 3) & 1) * 16 + kk * 32;
                uint32_t boffB = boffA + 16 * ROWSTRIDE;
                uint32_t bh[2][4];
                ldsm_x4(Wh + boffA, bh[0]);
                ldsm_x4(Wh + boffB, bh[1]);
                #pragma unroll
                for (int i = 0; i < 4; i++)
                    #pragma unroll
                    for (int j = 0; j < 4; j++)
                        mma_bf16(acc[br][i][j], ah[i], bh[j >> 1][(j & 1) * 2], bh[j >> 1][(j & 1) * 2 + 1]);
                #pragma unroll
                for (int i = 0; i < 4; i++)
                    #pragma unroll
                    for (int j = 0; j < 4; j++)
                        mma_bf16(acc[br][i][j], al[i], bh[j >> 1][(j & 1) * 2], bh[j >> 1][(j & 1) * 2 + 1]);
                uint32_t bl[2][4];
                ldsm_x4(Wl + boffA, bl[0]);
                ldsm_x4(Wl + boffB, bl[1]);
                #pragma unroll
                for (int i = 0; i < 4; i++)
                    #pragma unroll
                    for (int j = 0; j < 4; j++)
                        mma_bf16(acc[br][i][j], ah[i], bl[j >> 1][(j & 1) * 2], bl[j >> 1][(j & 1) * 2 + 1]);
            }
        }
    };
    auto mma_1br = [&](int br, int tAh, int tAl, int tWh, int tWl) {
        uint32_t Ah = sb + tAh * TILE_B, Al = sb + tAl * TILE_B;
        uint32_t Wh = sb + tWh * TILE_B, Wl = sb + tWl * TILE_B;
        #pragma unroll
        for (int kk = 0; kk < 4; kk++) {
            uint32_t ah[4][4], al[4][4];
            #pragma unroll
            for (int i = 0; i < 4; i++) {
                uint32_t off = (wm * 64 + i * 16 + (lane & 15)) * ROWSTRIDE
                             + (lane >> 4) * 16 + kk * 32;
                ldsm_x4(Ah + off, ah[i]);
                ldsm_x4(Al + off, al[i]);
            }
            uint32_t boffA = (wn * 32 + ((lane >> 4) * 8) + (lane & 7)) * ROWSTRIDE
                           + ((lane >> 3) & 1) * 16 + kk * 32;
            uint32_t boffB = boffA + 16 * ROWSTRIDE;
            uint32_t bh[2][4];
            ldsm_x4(Wh + boffA, bh[0]);
            ldsm_x4(Wh + boffB, bh[1]);
            #pragma unroll
            for (int i = 0; i < 4; i++)
                #pragma unroll
                for (int j = 0; j < 4; j++)
                    mma_bf16(acc[br][i][j], ah[i], bh[j >> 1][(j & 1) * 2], bh[j >> 1][(j & 1) * 2 + 1]);
            #pragma unroll
            for (int i = 0; i < 4; i++)
                #pragma unroll
                for (int j = 0; j < 4; j++)
                    mma_bf16(acc[br][i][j], al[i], bh[j >> 1][(j & 1) * 2], bh[j >> 1][(j & 1) * 2 + 1]);
            uint32_t bl[2][4];
            ldsm_x4(Wl + boffA, bl[0]);
            ldsm_x4(Wl + boffB, bl[1]);
            #pragma unroll
            for (int i = 0; i < 4; i++)
                #pragma unroll
                for (int j = 0; j < 4; j++)
                    mma_bf16(acc[br][i][j], ah[i], bl[j >> 1][(j & 1) * 2], bl[j >> 1][(j & 1) * 2 + 1]);
        }
    };

    // ---------------- layer 1: 6 K-chunks, double-buffered ----------------
    {
        float4 pf[8];
        fetchA(0, pf);
        cpasyncW0(0, 0);
        CP_COMMIT();
        storeA(0, pf);
        CP_WAIT0();
        __syncthreads();

        #pragma unroll 1
        for (int kc = 0; kc < 6; kc++) {
            int stage = kc & 1;
            if (kc < 5) {
                fetchA(kc + 1, pf);
                cpasyncW0(kc + 1, stage ^ 1);
                CP_COMMIT();
            }
            mma_2br(stage * 6);
            if (kc < 5) {
                storeA(stage ^ 1, pf);
                CP_WAIT0();
            }
            __syncthreads();
        }
    }

    // ---------------- epilogue 1: H = split(leaky(acc + b0)); load W1 b0 ---
    cpasyncW1(0);
    CP_COMMIT();
    {
        const int chunk = wn >> 1;
        #pragma unroll
        for (int br = 0; br < 2; br++) {
            int th = br ? (chunk ? 8 : 6) : (chunk ? 2 : 0);
            char* Hh = smem + th * TILE_B;
            char* Hl = Hh + TILE_B;
            const float* b0p = bias + br * 256;
            #pragma unroll
            for (int i = 0; i < 4; i++) {
                int r0 = wm * 64 + i * 16 + (lane >> 2);
                #pragma unroll
                for (int j = 0; j < 4; j++) {
                    int c  = wn * 32 + j * 8 + (lane & 3) * 2;
                    int cl = c & 63;
                    float2 bb = *(const float2*)(b0p + c);
                    float v0 = leaky(acc[br][i][j][0] + bb.x);
                    float v1 = leaky(acc[br][i][j][1] + bb.y);
                    float v2 = leaky(acc[br][i][j][2] + bb.x);
                    float v3 = leaky(acc[br][i][j][3] + bb.y);
                    uint32_t h01 = pack_bf16(v0, v1);
                    uint32_t h23 = pack_bf16(v2, v3);
                    __nv_bfloat162 q01 = reinterpret_cast<__nv_bfloat162&>(h01);
                    __nv_bfloat162 q23 = reinterpret_cast<__nv_bfloat162&>(h23);
                    uint32_t l01 = pack_bf16(v0 - __low2float(q01), v1 - __high2float(q01));
                    uint32_t l23 = pack_bf16(v2 - __low2float(q23), v3 - __high2float(q23));
                    *(uint32_t*)(Hh + r0 * ROWSTRIDE + cl * 2) = h01;
                    *(uint32_t*)(Hl + r0 * ROWSTRIDE + cl * 2) = l01;
                    *(uint32_t*)(Hh + (r0 + 8) * ROWSTRIDE + cl * 2) = h23;
                    *(uint32_t*)(Hl + (r0 + 8) * ROWSTRIDE + cl * 2) = l23;
                }
            }
        }
    }
    CP_WAIT0();
    __syncthreads();

    // ---------------- layer 2 branch 0 (node messages) ---------------------
    #pragma unroll
    for (int i = 0; i < 4; i++)
        #pragma unroll
        for (int j = 0; j < 4; j++)
            #pragma unroll
            for (int q = 0; q < 4; q++) acc[0][i][j][q] = 0.0f;
    mma_1br(0, 0, 1, 4, 5);
    mma_1br(0, 2, 3, 10, 11);
    __syncthreads();

    // ---------------- stage node-out; load W1 b1; TMA-reduce scatter -------
    cpasyncW1(1);
    CP_COMMIT();
    {
        char* stag = smem;   // tiles 0-3: 128 rows x 528B
        const float* b1p = bias + 128;
        #pragma unroll
        for (int i = 0; i < 4; i++) {
            int r0 = wm * 64 + i * 16 + (lane >> 2);
            #pragma unroll
            for (int j = 0; j < 4; j++) {
                int c = wn * 32 + j * 8 + (lane & 3) * 2;
                float2 bb = *(const float2*)(b1p + c);
                *(float2*)(stag + r0 * STAG_STRIDE + c * 4) =
                    make_float2(leaky(acc[0][i][j][0] + bb.x), leaky(acc[0][i][j][1] + bb.y));
                *(float2*)(stag + (r0 + 8) * STAG_STRIDE + c * 4) =
                    make_float2(leaky(acc[0][i][j][2] + bb.x), leaky(acc[0][i][j][3] + bb.y));
            }
        }
    }
    CP_WAIT0();
    __syncthreads();
    FENCE_PROXY_ASYNC();
    if (tid < 128 && (e0 + tid) < E) {
        const float* dst = new_nodes + (size_t)ridx[tid] * D;
        asm volatile("cp.reduce.async.bulk.global.shared::cta.bulk_group.add.f32 [%0], [%1], %2;"
                     :: "l"(dst), "r"(sb + tid * STAG_STRIDE), "r"(512) : "memory");
    }
    asm volatile("cp.async.bulk.commit_group;" ::: "memory");

    // ---------------- layer 2 branch 1 (edge update) ------------------------
    #pragma unroll
    for (int i = 0; i < 4; i++)
        #pragma unroll
        for (int j = 0; j < 4; j++)
            #pragma unroll
            for (int q = 0; q < 4; q++) acc[1][i][j][q] = 0.0f;
    mma_1br(1, 6, 7, 4, 5);
    mma_1br(1, 8, 9, 10, 11);

    {
        const float* b1p = bias + 384;
        #pragma unroll
        for (int i = 0; i < 4; i++) {
            int r0 = wm * 64 + i * 16 + (lane >> 2);
            #pragma unroll
            for (int j = 0; j < 4; j++) {
                int c = wn * 32 + j * 8 + (lane & 3) * 2;
                float2 bb = *(const float2*)(b1p + c);
                int eA = e0 + r0, eB = eA + 8;
                if (eA < E)
                    *(float2*)(new_edges + (size_t)eA * D + c) =
                        make_float2(leaky(acc[1][i][j][0] + bb.x), leaky(acc[1][i][j][1] + bb.y));
                if (eB < E)
                    *(float2*)(new_edges + (size_t)eB * D + c) =
                        make_float2(leaky(acc[1][i][j][2] + bb.x), leaky(acc[1][i][j][3] + bb.y));
            }
        }
    }
    asm volatile("cp.async.bulk.wait_group.read 0;" ::: "memory");
}

// ============================================================================
extern "C" void kernel_launch(void* const* d_in, const int* in_sizes, int n_in,
                              void* d_out, int out_size)
{
    const float* nodes     = (const float*)d_in[0];
    const float* edges     = (const float*)d_in[1];
    const float* globals_  = (const float*)d_in[2];
    const int*   senders   = (const int*)d_in[3];
    const int*   receivers = (const int*)d_in[4];
    const int*   n_node    = (const int*)d_in[5];
    const int*   n_edge    = (const int*)d_in[6];

    const float* node_W0 = (const float*)d_in[7];
    const float* node_b0 = (const float*)d_in[8];
    const float* node_W1 = (const float*)d_in[9];
    const float* node_b1 = (const float*)d_in[10];
    const float* edge_W0 = (const float*)d_in[11];
    const float* edge_b0 = (const float*)d_in[12];
    const float* edge_W1 = (const float*)d_in[13];
    const float* edge_b1 = (const float*)d_in[14];
    const float* glob_W0 = (const float*)d_in[15];
    const float* glob_b0 = (const float*)d_in[16];
    const float* glob_W1 = (const float*)d_in[17];
    const float* glob_b1 = (const float*)d_in[18];
    const float* gnode_W0 = (const float*)d_in[19];
    const float* gnode_b0 = (const float*)d_in[20];
    const float* gnode_W1 = (const float*)d_in[21];
    const float* gnode_b1 = (const float*)d_in[22];
    const float* gedge_W0 = (const float*)d_in[23];
    const float* gedge_b0 = (const float*)d_in[24];
    const float* gedge_W1 = (const float*)d_in[25];
    const float* gedge_b1 = (const float*)d_in[26];
    const float* fin_W0 = (const float*)d_in[27];
    const float* fin_b0 = (const float*)d_in[28];
    const float* fin_W1 = (const float*)d_in[29];
    const float* fin_b1 = (const float*)d_in[30];

    const int N = in_sizes[0] / D;
    const int E = in_sizes[3];
    const int G = in_sizes[5];

    float* new_nodes  = (float*)d_out;
    float* new_edges  = new_nodes + (size_t)N * D;
    float* new_global = new_edges + (size_t)E * D;

    // [0] zero segment-sum target
    int n4 = N * D / 4;
    zero_nodes_kernel<<<(n4 + 255) / 256, 256>>>((float4*)new_nodes, n4);

    // [1] weight prep
    prep_weights<<<512, 256>>>(node_W0, node_W1, edge_W0, edge_W1);

    // [2] per-graph partial sums
    dim3 gs(G, 2, 4);
    graph_sum_kernel<<<gs, 128>>>(nodes, edges, n_node, n_edge, G);

    // [3] global branch MLPs
    dim3 gb(G, 3);
    global_branch_kernel<<<gb, 128>>>(globals_,
        glob_W0, glob_b0, glob_W1, glob_b1,
        gnode_W0, gnode_b0, gnode_W1, gnode_b1,
        gedge_W0, gedge_b0, gedge_W1, gedge_b1);

    // [4] final global MLP
    global_final_kernel<<<G, 128>>>(fin_W0, fin_b0, fin_W1, fin_b1, new_global);

    // [5] main edge kernel (profiled slot)
    cudaFuncSetAttribute(edge_mma_kernel,
                         cudaFuncAttributeMaxDynamicSharedMemorySize, SMEM_BYTES);
    int grid = (E + 127) / 128;
    edge_mma_kernel<<<grid, 256, SMEM_BYTES>>>(
        nodes, edges, senders, receivers,
        node_b0, node_b1, edge_b0, edge_b1,
        new_nodes, new_edges, E);
}

// round 5
// speedup vs baseline: 5.1428x; 1.2546x over previous
#include <cuda_runtime.h>
#include <cuda_fp16.h>
#include <cstdint>

#define D 128
#define TILE_B 18432            // one [128 rows][64 fp16 cols] tile, 144B stride
#define ROWSTRIDE 144
#define NTILES 12
#define TILES_BYTES (NTILES * TILE_B)      // 221184
#define IDX_OFF  TILES_BYTES               // sidx[128], ridx[128]
#define BIAS_OFF (IDX_OFF + 1024)          // 512 floats
#define SMEM_BYTES (BIAS_OFF + 2048)       // 224256
#define STAG_STRIDE 528                    // node-out staging row stride (16B aligned)

__device__ __forceinline__ uint32_t smem_u32(const void* p) {
    uint32_t a;
    asm("{ .reg .u64 t; cvta.to.shared.u64 t, %1; cvt.u32.u64 %0, t; }" : "=r"(a) : "l"(p));
    return a;
}
__device__ __forceinline__ float leaky(float x) { return x > 0.0f ? x : 0.01f * x; }
__device__ __forceinline__ uint32_t pack_f16(float a, float b) {
    __half2 t = __floats2half2_rn(a, b);
    return reinterpret_cast<uint32_t&>(t);
}
__device__ __forceinline__ void ldsm_x4(uint32_t addr, uint32_t r[4]) {
    asm volatile("ldmatrix.sync.aligned.m8n8.x4.shared.b16 {%0,%1,%2,%3}, [%4];"
                 : "=r"(r[0]), "=r"(r[1]), "=r"(r[2]), "=r"(r[3]) : "r"(addr));
}
__device__ __forceinline__ void mma_f16(float* c, const uint32_t* a, uint32_t b0, uint32_t b1) {
    asm volatile("mma.sync.aligned.m16n8k16.row.col.f32.f16.f16.f32 "
                 "{%0,%1,%2,%3}, {%4,%5,%6,%7}, {%8,%9}, {%0,%1,%2,%3};"
                 : "+f"(c[0]), "+f"(c[1]), "+f"(c[2]), "+f"(c[3])
                 : "r"(a[0]), "r"(a[1]), "r"(a[2]), "r"(a[3]), "r"(b0), "r"(b1));
}
__device__ __forceinline__ void cp_async16(uint32_t saddr, const void* gaddr) {
    asm volatile("cp.async.cg.shared.global [%0], [%1], 16;" :: "r"(saddr), "l"(gaddr));
}
#define CP_COMMIT()  asm volatile("cp.async.commit_group;" ::: "memory")
#define CP_WAIT0()   asm volatile("cp.async.wait_group 0;" ::: "memory")
#define FENCE_PROXY_ASYNC() asm volatile("fence.proxy.async.shared::cta;" ::: "memory")

// ============================================================================
// Device scratch
// ============================================================================
__device__ __half g_W0T[2][128 * 384];   // [branch][n][k] transposed, single fp16
__device__ __half g_W1T[2][128 * 128];
__device__ float g_part[2][256][4][128]; // per-graph partial sums
__device__ float g_cat[256][384];        // concat of 3 global-branch MLPs

// ============================================================================
// [0] zero new_nodes
// ============================================================================
__global__ void zero_nodes_kernel(float4* __restrict__ p, int n4) {
    int i = blockIdx.x * 256 + threadIdx.x;
    if (i < n4) p[i] = make_float4(0.f, 0.f, 0.f, 0.f);
}

// ============================================================================
// [1] weight prep: transpose + fp16 convert
// ============================================================================
__global__ void prep_weights(const float* __restrict__ nW0, const float* __restrict__ nW1,
                             const float* __restrict__ eW0, const float* __restrict__ eW1)
{
    int i = blockIdx.x * 256 + threadIdx.x;
    if (i < 98304) {                      // W0T: 2 * 128*384
        int b = i / 49152, r = i % 49152;
        int n = r / 384, k = r % 384;
        g_W0T[b][n * 384 + k] = __float2half_rn((b ? eW0 : nW0)[k * 128 + n]);
    } else if (i < 131072) {              // W1T: 2 * 128*128
        int j = i - 98304;
        int b = j / 16384, r = j % 16384;
        int n = r / 128, k = r % 128;
        g_W1T[b][n * 128 + k] = __float2half_rn((b ? eW1 : nW1)[k * 128 + n]);
    }
}

// ============================================================================
// [2] per-graph segment partial sums (no atomics): grid (G, 2, 4), block 128
// ============================================================================
__global__ void graph_sum_kernel(const float* __restrict__ nodes,
                                 const float* __restrict__ edges,
                                 const int* __restrict__ n_node,
                                 const int* __restrict__ n_edge, int G)
{
    int g = blockIdx.x, which = blockIdx.y, part = blockIdx.z;
    const float* src = which ? edges : nodes;
    const int*  cnts = which ? n_edge : n_node;

    int start = 0;
    for (int i = 0; i < g; i++) start += cnts[i];
    int cnt = cnts[g];

    int d = threadIdx.x;
    float s0 = 0.f, s1 = 0.f, s2 = 0.f, s3 = 0.f;
    const float* p = src + (size_t)start * D + d;
    int i = part;
    for (; i + 3 * 4 < cnt; i += 16) {
        s0 += p[(size_t)i * D];
        s1 += p[(size_t)(i + 4) * D];
        s2 += p[(size_t)(i + 8) * D];
        s3 += p[(size_t)(i + 12) * D];
    }
    for (; i < cnt; i += 4) s0 += p[(size_t)i * D];
    g_part[which][g][part][d] = s0 + s1 + s2 + s3;
}

// ============================================================================
// [3] global branch MLPs: grid (G, 3), block 128 -> g_cat
// ============================================================================
__global__ void global_branch_kernel(const float* __restrict__ globals_,
                                     const float* gW0, const float* gb0, const float* gW1, const float* gb1,
                                     const float* nW0, const float* nb0, const float* nW1, const float* nb1,
                                     const float* eW0, const float* eb0, const float* eW1, const float* eb1)
{
    __shared__ float in[D];
    __shared__ float h[D];
    int g = blockIdx.x, b = blockIdx.y, d = threadIdx.x;

    const float *W0, *b0, *W1, *b1;
    if (b == 0)      { W0 = gW0; b0 = gb0; W1 = gW1; b1 = gb1;
                       in[d] = globals_[(size_t)g * D + d]; }
    else if (b == 1) { W0 = nW0; b0 = nb0; W1 = nW1; b1 = nb1;
                       in[d] = g_part[0][g][0][d] + g_part[0][g][1][d]
                             + g_part[0][g][2][d] + g_part[0][g][3][d]; }
    else             { W0 = eW0; b0 = eb0; W1 = eW1; b1 = eb1;
                       in[d] = g_part[1][g][0][d] + g_part[1][g][1][d]
                             + g_part[1][g][2][d] + g_part[1][g][3][d]; }
    __syncthreads();

    float a0 = 0.f, a1 = 0.f, a2 = 0.f, a3 = 0.f;
    #pragma unroll 8
    for (int k = 0; k < D; k += 4) {
        a0 = fmaf(in[k],     __ldg(W0 + k * D + d),       a0);
        a1 = fmaf(in[k + 1], __ldg(W0 + (k + 1) * D + d), a1);
        a2 = fmaf(in[k + 2], __ldg(W0 + (k + 2) * D + d), a2);
        a3 = fmaf(in[k + 3], __ldg(W0 + (k + 3) * D + d), a3);
    }
    h[d] = leaky((a0 + a1) + (a2 + a3) + __ldg(b0 + d));
    __syncthreads();

    a0 = a1 = a2 = a3 = 0.f;
    #pragma unroll 8
    for (int k = 0; k < D; k += 4) {
        a0 = fmaf(h[k],     __ldg(W1 + k * D + d),       a0);
        a1 = fmaf(h[k + 1], __ldg(W1 + (k + 1) * D + d), a1);
        a2 = fmaf(h[k + 2], __ldg(W1 + (k + 2) * D + d), a2);
        a3 = fmaf(h[k + 3], __ldg(W1 + (k + 3) * D + d), a3);
    }
    g_cat[g][b * D + d] = leaky((a0 + a1) + (a2 + a3) + __ldg(b1 + d));
}

// ============================================================================
// [4] final global MLP: grid G, block 128
// ============================================================================
__global__ void global_final_kernel(const float* fW0, const float* fb0,
                                    const float* fW1, const float* fb1,
                                    float* __restrict__ out_global)
{
    __shared__ float cat[3 * D];
    __shared__ float h[D];
    int g = blockIdx.x, d = threadIdx.x;
    cat[d]         = g_cat[g][d];
    cat[D + d]     = g_cat[g][D + d];
    cat[2 * D + d] = g_cat[g][2 * D + d];
    __syncthreads();

    float a0 = 0.f, a1 = 0.f, a2 = 0.f, a3 = 0.f;
    #pragma unroll 8
    for (int k = 0; k < 3 * D; k += 4) {
        a0 = fmaf(cat[k],     __ldg(fW0 + k * D + d),       a0);
        a1 = fmaf(cat[k + 1], __ldg(fW0 + (k + 1) * D + d), a1);
        a2 = fmaf(cat[k + 2], __ldg(fW0 + (k + 2) * D + d), a2);
        a3 = fmaf(cat[k + 3], __ldg(fW0 + (k + 3) * D + d), a3);
    }
    h[d] = leaky((a0 + a1) + (a2 + a3) + __ldg(fb0 + d));
    __syncthreads();

    a0 = a1 = a2 = a3 = 0.f;
    #pragma unroll 8
    for (int k = 0; k < D; k += 4) {
        a0 = fmaf(h[k],     __ldg(fW1 + k * D + d),       a0);
        a1 = fmaf(h[k + 1], __ldg(fW1 + (k + 1) * D + d), a1);
        a2 = fmaf(h[k + 2], __ldg(fW1 + (k + 2) * D + d), a2);
        a3 = fmaf(h[k + 3], __ldg(fW1 + (k + 3) * D + d), a3);
    }
    out_global[(size_t)g * D + d] = leaky((a0 + a1) + (a2 + a3) + __ldg(fb1 + d));
}

// ============================================================================
// [5] main fused edge kernel: mma.sync fp16, split-A 2-pass
// Tile map:
//   Layer1 stage s: s*4 + {0:Ah, 1:Al, 2:Wn, 3:We}  (tiles 0-7)
//   W1 (preloaded once): 8:Wn1_c0, 9:Wn1_c1, 10:We1_c0, 11:We1_c1
//   Layer2 H: node ch0->0,1  ch1->2,3 ; edge ch0->4,5  ch1->6,7
//   Node-out staging reuses tiles 0-3 (node H consumed before).
// ============================================================================
__global__ __launch_bounds__(256, 1)
void edge_mma_kernel(const float* __restrict__ nodes,
                     const float* __restrict__ edges,
                     const int*   __restrict__ senders,
                     const int*   __restrict__ receivers,
                     const float* __restrict__ nb0f, const float* __restrict__ nb1f,
                     const float* __restrict__ eb0f, const float* __restrict__ eb1f,
                     float* __restrict__ new_nodes,
                     float* __restrict__ new_edges,
                     int E)
{
    extern __shared__ char smem[];
    const uint32_t sb = smem_u32(smem);
    const int tid  = threadIdx.x;
    const int wid  = tid >> 5;
    const int lane = tid & 31;
    const int wm   = wid >> 2;        // 0..1  (M offset wm*64)
    const int wn   = wid & 3;         // 0..3  (N offset wn*32)
    const int e0   = blockIdx.x * 128;

    int*   sidx = (int*)(smem + IDX_OFF);
    int*   ridx = (int*)(smem + IDX_OFF + 512);
    float* bias = (float*)(smem + BIAS_OFF);

    if (tid < 128) {
        int e  = e0 + tid;
        int ec = e < E ? e : E - 1;
        sidx[tid] = senders[ec];
        ridx[tid] = receivers[ec];
        bias[tid]       = nb0f[tid];
        bias[128 + tid] = nb1f[tid];
        bias[256 + tid] = eb0f[tid];
        bias[384 + tid] = eb1f[tid];
    }
    __syncthreads();

    float acc[2][4][4][4];
    #pragma unroll
    for (int b = 0; b < 2; b++)
        #pragma unroll
        for (int i = 0; i < 4; i++)
            #pragma unroll
            for (int j = 0; j < 4; j++)
                #pragma unroll
                for (int q = 0; q < 4; q++) acc[b][i][j][q] = 0.0f;

    auto fetchA = [&](int kc, float4 pf[8]) {
        int row = tid >> 1;
        const float* bp;
        int sec = kc >> 1;
        if (sec == 0)      bp = nodes + (size_t)sidx[row] * D;
        else if (sec == 1) bp = nodes + (size_t)ridx[row] * D;
        else { int e = e0 + row; int ec = e < E ? e : E - 1; bp = edges + (size_t)ec * D; }
        bp += (kc & 1) * 64;
        const float4* p4 = (const float4*)bp + (tid & 1) * 8;
        #pragma unroll
        for (int i = 0; i < 8; i++) pf[i] = p4[i];
    };
    auto storeA = [&](int stage, const float4 pf[8]) {
        int row = tid >> 1;
        char* Ah = smem + (stage * 4 + 0) * TILE_B;
        char* Al = smem + (stage * 4 + 1) * TILE_B;
        #pragma unroll
        for (int i = 0; i < 8; i++) {
            float4 x = pf[i];
            uint32_t h0 = pack_f16(x.x, x.y);
            uint32_t h1 = pack_f16(x.z, x.w);
            __half2 hh0 = reinterpret_cast<__half2&>(h0);
            __half2 hh1 = reinterpret_cast<__half2&>(h1);
            uint32_t l0 = pack_f16(x.x - __low2float(hh0), x.y - __high2float(hh0));
            uint32_t l1 = pack_f16(x.z - __low2float(hh1), x.w - __high2float(hh1));
            uint32_t off = row * ROWSTRIDE + ((tid & 1) * 8 + i) * 8;
            *(uint2*)(Ah + off) = make_uint2(h0, h1);
            *(uint2*)(Al + off) = make_uint2(l0, l1);
        }
    };
    auto cpasyncW0 = [&](int kc, int stage) {
        const char* gp[2] = {(const char*)g_W0T[0], (const char*)g_W0T[1]};
        #pragma unroll
        for (int u = 0; u < 8; u++) {
            int i = tid + u * 256;
            int t = i >> 10, r = i & 1023, n = r >> 3, q = r & 7;
            cp_async16(sb + (stage * 4 + 2 + t) * TILE_B + n * ROWSTRIDE + q * 16,
                       gp[t] + n * 768 + kc * 128 + q * 16);
        }
    };
    auto cpasyncW1_once = [&]() {
        #pragma unroll
        for (int u = 0; u < 16; u++) {
            int i = tid + u * 256;
            int t = i >> 10;                 // 0..3 -> tiles 8..11
            int br = t >> 1, c = t & 1;
            int r = i & 1023, n = r >> 3, q = r & 7;
            cp_async16(sb + (8 + t) * TILE_B + n * ROWSTRIDE + q * 16,
                       (const char*)g_W1T[br] + n * 256 + c * 128 + q * 16);
        }
    };
    // layer-1 MMA: both branches, 2 passes (Ah*W, Al*W)
    auto mma_2br = [&](int base) {
        uint32_t Ah = sb + (base + 0) * TILE_B, Al = sb + (base + 1) * TILE_B;
        #pragma unroll
        for (int kk = 0; kk < 4; kk++) {
            uint32_t ah[4][4], al[4][4];
            #pragma unroll
            for (int i = 0; i < 4; i++) {
                uint32_t off = (wm * 64 + i * 16 + (lane & 15)) * ROWSTRIDE
                             + (lane >> 4) * 16 + kk * 32;
                ldsm_x4(Ah + off, ah[i]);
                ldsm_x4(Al + off, al[i]);
            }
            #pragma unroll
            for (int br = 0; br < 2; br++) {
                uint32_t W = sb + (base + 2 + br) * TILE_B;
                uint32_t boffA = (wn * 32 + ((lane >> 4) * 8) + (lane & 7)) * ROWSTRIDE
                               + ((lane >> 3) & 1) * 16 + kk * 32;
                uint32_t boffB = boffA + 16 * ROWSTRIDE;
                uint32_t bh[2][4];
                ldsm_x4(W + boffA, bh[0]);
                ldsm_x4(W + boffB, bh[1]);
                #pragma unroll
                for (int i = 0; i < 4; i++)
                    #pragma unroll
                    for (int j = 0; j < 4; j++)
                        mma_f16(acc[br][i][j], ah[i], bh[j >> 1][(j & 1) * 2], bh[j >> 1][(j & 1) * 2 + 1]);
                #pragma unroll
                for (int i = 0; i < 4; i++)
                    #pragma unroll
                    for (int j = 0; j < 4; j++)
                        mma_f16(acc[br][i][j], al[i], bh[j >> 1][(j & 1) * 2], bh[j >> 1][(j & 1) * 2 + 1]);
            }
        }
    };
    // layer-2 MMA: one branch, one 64-k chunk, 2 passes
    auto mma_1br = [&](int br, int tHh, int tHl, int tW) {
        uint32_t Ah = sb + tHh * TILE_B, Al = sb + tHl * TILE_B;
        uint32_t W  = sb + tW * TILE_B;
        #pragma unroll
        for (int kk = 0; kk < 4; kk++) {
            uint32_t ah[4][4], al[4][4];
            #pragma unroll
            for (int i = 0; i < 4; i++) {
                uint32_t off = (wm * 64 + i * 16 + (lane & 15)) * ROWSTRIDE
                             + (lane >> 4) * 16 + kk * 32;
                ldsm_x4(Ah + off, ah[i]);
                ldsm_x4(Al + off, al[i]);
            }
            uint32_t boffA = (wn * 32 + ((lane >> 4) * 8) + (lane & 7)) * ROWSTRIDE
                           + ((lane >> 3) & 1) * 16 + kk * 32;
            uint32_t boffB = boffA + 16 * ROWSTRIDE;
            uint32_t bh[2][4];
            ldsm_x4(W + boffA, bh[0]);
            ldsm_x4(W + boffB, bh[1]);
            #pragma unroll
            for (int i = 0; i < 4; i++)
                #pragma unroll
                for (int j = 0; j < 4; j++)
                    mma_f16(acc[br][i][j], ah[i], bh[j >> 1][(j & 1) * 2], bh[j >> 1][(j & 1) * 2 + 1]);
            #pragma unroll
            for (int i = 0; i < 4; i++)
                #pragma unroll
                for (int j = 0; j < 4; j++)
                    mma_f16(acc[br][i][j], al[i], bh[j >> 1][(j & 1) * 2], bh[j >> 1][(j & 1) * 2 + 1]);
        }
    };

    // ---------------- layer 1: 6 K-chunks, double-buffered ----------------
    {
        float4 pf[8];
        fetchA(0, pf);
        cpasyncW1_once();               // tiles 8-11, live until layer 2
        cpasyncW0(0, 0);
        CP_COMMIT();
        storeA(0, pf);
        CP_WAIT0();
        __syncthreads();

        #pragma unroll 1
        for (int kc = 0; kc < 6; kc++) {
            int stage = kc & 1;
            if (kc < 5) {
                fetchA(kc + 1, pf);
                cpasyncW0(kc + 1, stage ^ 1);
                CP_COMMIT();
            }
            mma_2br(stage * 4);
            if (kc < 5) {
                storeA(stage ^ 1, pf);
                CP_WAIT0();
            }
            __syncthreads();
        }
    }

    // ---------------- epilogue 1: H = split(leaky(acc + b0)) ---------------
    {
        const int chunk = wn >> 1;
        #pragma unroll
        for (int br = 0; br < 2; br++) {
            int th = (br ? 4 : 0) + 2 * chunk;
            char* Hh = smem + th * TILE_B;
            char* Hl = Hh + TILE_B;
            const float* b0p = bias + br * 256;
            #pragma unroll
            for (int i = 0; i < 4; i++) {
                int r0 = wm * 64 + i * 16 + (lane >> 2);
                #pragma unroll
                for (int j = 0; j < 4; j++) {
                    int c  = wn * 32 + j * 8 + (lane & 3) * 2;
                    int cl = c & 63;
                    float2 bb = *(const float2*)(b0p + c);
                    float v0 = leaky(acc[br][i][j][0] + bb.x);
                    float v1 = leaky(acc[br][i][j][1] + bb.y);
                    float v2 = leaky(acc[br][i][j][2] + bb.x);
                    float v3 = leaky(acc[br][i][j][3] + bb.y);
                    uint32_t h01 = pack_f16(v0, v1);
                    uint32_t h23 = pack_f16(v2, v3);
                    __half2 q01 = reinterpret_cast<__half2&>(h01);
                    __half2 q23 = reinterpret_cast<__half2&>(h23);
                    uint32_t l01 = pack_f16(v0 - __low2float(q01), v1 - __high2float(q01));
                    uint32_t l23 = pack_f16(v2 - __low2float(q23), v3 - __high2float(q23));
                    *(uint32_t*)(Hh + r0 * ROWSTRIDE + cl * 2) = h01;
                    *(uint32_t*)(Hl + r0 * ROWSTRIDE + cl * 2) = l01;
                    *(uint32_t*)(Hh + (r0 + 8) * ROWSTRIDE + cl * 2) = h23;
                    *(uint32_t*)(Hl + (r0 + 8) * ROWSTRIDE + cl * 2) = l23;
                }
            }
        }
    }
    __syncthreads();

    // ---------------- layer 2 branch 0 (node messages) ---------------------
    #pragma unroll
    for (int i = 0; i < 4; i++)
        #pragma unroll
        for (int j = 0; j < 4; j++)
            #pragma unroll
            for (int q = 0; q < 4; q++) acc[0][i][j][q] = 0.0f;
    mma_1br(0, 0, 1, 8);
    mma_1br(0, 2, 3, 9);
    __syncthreads();

    // ---------------- stage node-out; TMA-reduce scatter --------------------
    {
        char* stag = smem;   // tiles 0-3: 128 rows x 528B (node H consumed)
        const float* b1p = bias + 128;
        #pragma unroll
        for (int i = 0; i < 4; i++) {
            int r0 = wm * 64 + i * 16 + (lane >> 2);
            #pragma unroll
            for (int j = 0; j < 4; j++) {
                int c = wn * 32 + j * 8 + (lane & 3) * 2;
                float2 bb = *(const float2*)(b1p + c);
                *(float2*)(stag + r0 * STAG_STRIDE + c * 4) =
                    make_float2(leaky(acc[0][i][j][0] + bb.x), leaky(acc[0][i][j][1] + bb.y));
                *(float2*)(stag + (r0 + 8) * STAG_STRIDE + c * 4) =
                    make_float2(leaky(acc[0][i][j][2] + bb.x), leaky(acc[0][i][j][3] + bb.y));
            }
        }
    }
    __syncthreads();
    FENCE_PROXY_ASYNC();
    if (tid < 128 && (e0 + tid) < E) {
        const float* dst = new_nodes + (size_t)ridx[tid] * D;
        asm volatile("cp.reduce.async.bulk.global.shared::cta.bulk_group.add.f32 [%0], [%1], %2;"
                     :: "l"(dst), "r"(sb + tid * STAG_STRIDE), "r"(512) : "memory");
    }
    asm volatile("cp.async.bulk.commit_group;" ::: "memory");

    // ---------------- layer 2 branch 1 (edge update) ------------------------
    #pragma unroll
    for (int i = 0; i < 4; i++)
        #pragma unroll
        for (int j = 0; j < 4; j++)
            #pragma unroll
            for (int q = 0; q < 4; q++) acc[1][i][j][q] = 0.0f;
    mma_1br(1, 4, 5, 10);
    mma_1br(1, 6, 7, 11);

    {
        const float* b1p = bias + 384;
        #pragma unroll
        for (int i = 0; i < 4; i++) {
            int r0 = wm * 64 + i * 16 + (lane >> 2);
            #pragma unroll
            for (int j = 0; j < 4; j++) {
                int c = wn * 32 + j * 8 + (lane & 3) * 2;
                float2 bb = *(const float2*)(b1p + c);
                int eA = e0 + r0, eB = eA + 8;
                if (eA < E)
                    *(float2*)(new_edges + (size_t)eA * D + c) =
                        make_float2(leaky(acc[1][i][j][0] + bb.x), leaky(acc[1][i][j][1] + bb.y));
                if (eB < E)
                    *(float2*)(new_edges + (size_t)eB * D + c) =
                        make_float2(leaky(acc[1][i][j][2] + bb.x), leaky(acc[1][i][j][3] + bb.y));
            }
        }
    }
    asm volatile("cp.async.bulk.wait_group.read 0;" ::: "memory");
}

// ============================================================================
extern "C" void kernel_launch(void* const* d_in, const int* in_sizes, int n_in,
                              void* d_out, int out_size)
{
    const float* nodes     = (const float*)d_in[0];
    const float* edges     = (const float*)d_in[1];
    const float* globals_  = (const float*)d_in[2];
    const int*   senders   = (const int*)d_in[3];
    const int*   receivers = (const int*)d_in[4];
    const int*   n_node    = (const int*)d_in[5];
    const int*   n_edge    = (const int*)d_in[6];

    const float* node_W0 = (const float*)d_in[7];
    const float* node_b0 = (const float*)d_in[8];
    const float* node_W1 = (const float*)d_in[9];
    const float* node_b1 = (const float*)d_in[10];
    const float* edge_W0 = (const float*)d_in[11];
    const float* edge_b0 = (const float*)d_in[12];
    const float* edge_W1 = (const float*)d_in[13];
    const float* edge_b1 = (const float*)d_in[14];
    const float* glob_W0 = (const float*)d_in[15];
    const float* glob_b0 = (const float*)d_in[16];
    const float* glob_W1 = (const float*)d_in[17];
    const float* glob_b1 = (const float*)d_in[18];
    const float* gnode_W0 = (const float*)d_in[19];
    const float* gnode_b0 = (const float*)d_in[20];
    const float* gnode_W1 = (const float*)d_in[21];
    const float* gnode_b1 = (const float*)d_in[22];
    const float* gedge_W0 = (const float*)d_in[23];
    const float* gedge_b0 = (const float*)d_in[24];
    const float* gedge_W1 = (const float*)d_in[25];
    const float* gedge_b1 = (const float*)d_in[26];
    const float* fin_W0 = (const float*)d_in[27];
    const float* fin_b0 = (const float*)d_in[28];
    const float* fin_W1 = (const float*)d_in[29];
    const float* fin_b1 = (const float*)d_in[30];

    const int N = in_sizes[0] / D;
    const int E = in_sizes[3];
    const int G = in_sizes[5];

    float* new_nodes  = (float*)d_out;
    float* new_edges  = new_nodes + (size_t)N * D;
    float* new_global = new_edges + (size_t)E * D;

    // [0] zero segment-sum target
    int n4 = N * D / 4;
    zero_nodes_kernel<<<(n4 + 255) / 256, 256>>>((float4*)new_nodes, n4);

    // [1] weight prep
    prep_weights<<<512, 256>>>(node_W0, node_W1, edge_W0, edge_W1);

    // [2] per-graph partial sums
    dim3 gs(G, 2, 4);
    graph_sum_kernel<<<gs, 128>>>(nodes, edges, n_node, n_edge, G);

    // [3] global branch MLPs
    dim3 gb(G, 3);
    global_branch_kernel<<<gb, 128>>>(globals_,
        glob_W0, glob_b0, glob_W1, glob_b1,
        gnode_W0, gnode_b0, gnode_W1, gnode_b1,
        gedge_W0, gedge_b0, gedge_W1, gedge_b1);

    // [4] final global MLP
    global_final_kernel<<<G, 128>>>(fin_W0, fin_b0, fin_W1, fin_b1, new_global);

    // [5] main edge kernel
    cudaFuncSetAttribute(edge_mma_kernel,
                         cudaFuncAttributeMaxDynamicSharedMemorySize, SMEM_BYTES);
    int grid = (E + 127) / 128;
    edge_mma_kernel<<<grid, 256, SMEM_BYTES>>>(
        nodes, edges, senders, receivers,
        node_b0, node_b1, edge_b0, edge_b1,
        new_nodes, new_edges, E);
}

// round 6
// speedup vs baseline: 7.2303x; 1.4059x over previous
#include <cuda_runtime.h>
#include <cuda_fp16.h>
#include <cstdint>

#define D 128
#define TILE_B 18432            // one [128 rows][64 fp16 cols] tile, 144B stride
#define ROWSTRIDE 144
#define NTILES 10
#define TILES_BYTES (NTILES * TILE_B)      // 184320
#define IDX_OFF  TILES_BYTES               // sidx[128], ridx[128]
#define BIAS_OFF (IDX_OFF + 1024)          // 512 floats
#define SMEM_BYTES (BIAS_OFF + 2048)       // 187392
#define STAG_STRIDE 528                    // node-out staging row stride (16B aligned)

__device__ __forceinline__ uint32_t smem_u32(const void* p) {
    uint32_t a;
    asm("{ .reg .u64 t; cvta.to.shared.u64 t, %1; cvt.u32.u64 %0, t; }" : "=r"(a) : "l"(p));
    return a;
}
__device__ __forceinline__ float leaky(float x) { return x > 0.0f ? x : 0.01f * x; }
__device__ __forceinline__ uint32_t pack_f16(float a, float b) {
    __half2 t = __floats2half2_rn(a, b);
    return reinterpret_cast<uint32_t&>(t);
}
__device__ __forceinline__ void ldsm_x4(uint32_t addr, uint32_t r[4]) {
    asm volatile("ldmatrix.sync.aligned.m8n8.x4.shared.b16 {%0,%1,%2,%3}, [%4];"
                 : "=r"(r[0]), "=r"(r[1]), "=r"(r[2]), "=r"(r[3]) : "r"(addr));
}
__device__ __forceinline__ void mma_f16(float* c, const uint32_t* a, uint32_t b0, uint32_t b1) {
    asm volatile("mma.sync.aligned.m16n8k16.row.col.f32.f16.f16.f32 "
                 "{%0,%1,%2,%3}, {%4,%5,%6,%7}, {%8,%9}, {%0,%1,%2,%3};"
                 : "+f"(c[0]), "+f"(c[1]), "+f"(c[2]), "+f"(c[3])
                 : "r"(a[0]), "r"(a[1]), "r"(a[2]), "r"(a[3]), "r"(b0), "r"(b1));
}
__device__ __forceinline__ void cp_async16(uint32_t saddr, const void* gaddr) {
    asm volatile("cp.async.cg.shared.global [%0], [%1], 16;" :: "r"(saddr), "l"(gaddr));
}
#define CP_COMMIT()  asm volatile("cp.async.commit_group;" ::: "memory")
#define CP_WAIT0()   asm volatile("cp.async.wait_group 0;" ::: "memory")
#define FENCE_PROXY_ASYNC() asm volatile("fence.proxy.async.shared::cta;" ::: "memory")

// ============================================================================
// Device scratch
// ============================================================================
__device__ __half g_W0T[2][128 * 384];   // [branch][n][k] transposed fp16
__device__ __half g_W1T[2][128 * 128];
__device__ float g_part[2][256][4][128]; // per-graph partial sums
__device__ float g_cat[256][384];        // concat of 3 global-branch MLPs

// ============================================================================
// [0] zero new_nodes
// ============================================================================
__global__ void zero_nodes_kernel(float4* __restrict__ p, int n4) {
    int i = blockIdx.x * 256 + threadIdx.x;
    if (i < n4) p[i] = make_float4(0.f, 0.f, 0.f, 0.f);
}

// ============================================================================
// [1] weight prep: transpose + fp16 convert
// ============================================================================
__global__ void prep_weights(const float* __restrict__ nW0, const float* __restrict__ nW1,
                             const float* __restrict__ eW0, const float* __restrict__ eW1)
{
    int i = blockIdx.x * 256 + threadIdx.x;
    if (i < 98304) {                      // W0T: 2 * 128*384
        int b = i / 49152, r = i % 49152;
        int n = r / 384, k = r % 384;
        g_W0T[b][n * 384 + k] = __float2half_rn((b ? eW0 : nW0)[k * 128 + n]);
    } else if (i < 131072) {              // W1T: 2 * 128*128
        int j = i - 98304;
        int b = j / 16384, r = j % 16384;
        int n = r / 128, k = r % 128;
        g_W1T[b][n * 128 + k] = __float2half_rn((b ? eW1 : nW1)[k * 128 + n]);
    }
}

// ============================================================================
// [2] per-graph segment partial sums: grid (G, 2, 4), block 128
// ============================================================================
__global__ void graph_sum_kernel(const float* __restrict__ nodes,
                                 const float* __restrict__ edges,
                                 const int* __restrict__ n_node,
                                 const int* __restrict__ n_edge, int G)
{
    int g = blockIdx.x, which = blockIdx.y, part = blockIdx.z;
    const float* src = which ? edges : nodes;
    const int*  cnts = which ? n_edge : n_node;

    int start = 0;
    for (int i = 0; i < g; i++) start += cnts[i];
    int cnt = cnts[g];

    int d = threadIdx.x;
    float s0 = 0.f, s1 = 0.f, s2 = 0.f, s3 = 0.f;
    const float* p = src + (size_t)start * D + d;
    int i = part;
    for (; i + 3 * 4 < cnt; i += 16) {
        s0 += p[(size_t)i * D];
        s1 += p[(size_t)(i + 4) * D];
        s2 += p[(size_t)(i + 8) * D];
        s3 += p[(size_t)(i + 12) * D];
    }
    for (; i < cnt; i += 4) s0 += p[(size_t)i * D];
    g_part[which][g][part][d] = s0 + s1 + s2 + s3;
}

// ============================================================================
// [3] global branch MLPs: grid (G, 3), block 128 -> g_cat
// ============================================================================
__global__ void global_branch_kernel(const float* __restrict__ globals_,
                                     const float* gW0, const float* gb0, const float* gW1, const float* gb1,
                                     const float* nW0, const float* nb0, const float* nW1, const float* nb1,
                                     const float* eW0, const float* eb0, const float* eW1, const float* eb1)
{
    __shared__ float in[D];
    __shared__ float h[D];
    int g = blockIdx.x, b = blockIdx.y, d = threadIdx.x;

    const float *W0, *b0, *W1, *b1;
    if (b == 0)      { W0 = gW0; b0 = gb0; W1 = gW1; b1 = gb1;
                       in[d] = globals_[(size_t)g * D + d]; }
    else if (b == 1) { W0 = nW0; b0 = nb0; W1 = nW1; b1 = nb1;
                       in[d] = g_part[0][g][0][d] + g_part[0][g][1][d]
                             + g_part[0][g][2][d] + g_part[0][g][3][d]; }
    else             { W0 = eW0; b0 = eb0; W1 = eW1; b1 = eb1;
                       in[d] = g_part[1][g][0][d] + g_part[1][g][1][d]
                             + g_part[1][g][2][d] + g_part[1][g][3][d]; }
    __syncthreads();

    float a0 = 0.f, a1 = 0.f, a2 = 0.f, a3 = 0.f;
    #pragma unroll 8
    for (int k = 0; k < D; k += 4) {
        a0 = fmaf(in[k],     __ldg(W0 + k * D + d),       a0);
        a1 = fmaf(in[k + 1], __ldg(W0 + (k + 1) * D + d), a1);
        a2 = fmaf(in[k + 2], __ldg(W0 + (k + 2) * D + d), a2);
        a3 = fmaf(in[k + 3], __ldg(W0 + (k + 3) * D + d), a3);
    }
    h[d] = leaky((a0 + a1) + (a2 + a3) + __ldg(b0 + d));
    __syncthreads();

    a0 = a1 = a2 = a3 = 0.f;
    #pragma unroll 8
    for (int k = 0; k < D; k += 4) {
        a0 = fmaf(h[k],     __ldg(W1 + k * D + d),       a0);
        a1 = fmaf(h[k + 1], __ldg(W1 + (k + 1) * D + d), a1);
        a2 = fmaf(h[k + 2], __ldg(W1 + (k + 2) * D + d), a2);
        a3 = fmaf(h[k + 3], __ldg(W1 + (k + 3) * D + d), a3);
    }
    g_cat[g][b * D + d] = leaky((a0 + a1) + (a2 + a3) + __ldg(b1 + d));
}

// ============================================================================
// [4] final global MLP: grid G, block 128
// ============================================================================
__global__ void global_final_kernel(const float* fW0, const float* fb0,
                                    const float* fW1, const float* fb1,
                                    float* __restrict__ out_global)
{
    __shared__ float cat[3 * D];
    __shared__ float h[D];
    int g = blockIdx.x, d = threadIdx.x;
    cat[d]         = g_cat[g][d];
    cat[D + d]     = g_cat[g][D + d];
    cat[2 * D + d] = g_cat[g][2 * D + d];
    __syncthreads();

    float a0 = 0.f, a1 = 0.f, a2 = 0.f, a3 = 0.f;
    #pragma unroll 8
    for (int k = 0; k < 3 * D; k += 4) {
        a0 = fmaf(cat[k],     __ldg(fW0 + k * D + d),       a0);
        a1 = fmaf(cat[k + 1], __ldg(fW0 + (k + 1) * D + d), a1);
        a2 = fmaf(cat[k + 2], __ldg(fW0 + (k + 2) * D + d), a2);
        a3 = fmaf(cat[k + 3], __ldg(fW0 + (k + 3) * D + d), a3);
    }
    h[d] = leaky((a0 + a1) + (a2 + a3) + __ldg(fb0 + d));
    __syncthreads();

    a0 = a1 = a2 = a3 = 0.f;
    #pragma unroll 8
    for (int k = 0; k < D; k += 4) {
        a0 = fmaf(h[k],     __ldg(fW1 + k * D + d),       a0);
        a1 = fmaf(h[k + 1], __ldg(fW1 + (k + 1) * D + d), a1);
        a2 = fmaf(h[k + 2], __ldg(fW1 + (k + 2) * D + d), a2);
        a3 = fmaf(h[k + 3], __ldg(fW1 + (k + 3) * D + d), a3);
    }
    out_global[(size_t)g * D + d] = leaky((a0 + a1) + (a2 + a3) + __ldg(fb1 + d));
}

// ============================================================================
// [5] main fused edge kernel: pure fp16 mma.sync, single-pass
// Tile map (10 tiles):
//   layer1 stage s: s*3 + {0:A, 1:Wn, 2:We}        (tiles 0-5)
//   W1 preloaded:   6:Wn1_c0, 7:Wn1_c1, 8:We1_c0, 9:We1_c1
//   layer2 H: node c0->0, c1->1 ; edge c0->2, c1->3
//   node-out staging: wm0 rows (0-63) -> tiles 0-1 ; wm1 rows (64-127) -> tiles 6-7
// ============================================================================
__global__ __launch_bounds__(256, 1)
void edge_mma_kernel(const float* __restrict__ nodes,
                     const float* __restrict__ edges,
                     const int*   __restrict__ senders,
                     const int*   __restrict__ receivers,
                     const float* __restrict__ nb0f, const float* __restrict__ nb1f,
                     const float* __restrict__ eb0f, const float* __restrict__ eb1f,
                     float* __restrict__ new_nodes,
                     float* __restrict__ new_edges,
                     int E)
{
    extern __shared__ char smem[];
    const uint32_t sb = smem_u32(smem);
    const int tid  = threadIdx.x;
    const int wid  = tid >> 5;
    const int lane = tid & 31;
    const int wm   = wid >> 2;        // 0..1  (M offset wm*64)
    const int wn   = wid & 3;         // 0..3  (N offset wn*32)
    const int e0   = blockIdx.x * 128;

    int*   sidx = (int*)(smem + IDX_OFF);
    int*   ridx = (int*)(smem + IDX_OFF + 512);
    float* bias = (float*)(smem + BIAS_OFF);

    if (tid < 128) {
        int e  = e0 + tid;
        int ec = e < E ? e : E - 1;
        sidx[tid] = senders[ec];
        ridx[tid] = receivers[ec];
        bias[tid]       = nb0f[tid];
        bias[128 + tid] = nb1f[tid];
        bias[256 + tid] = eb0f[tid];
        bias[384 + tid] = eb1f[tid];
    }
    __syncthreads();

    float acc[2][4][4][4];
    #pragma unroll
    for (int b = 0; b < 2; b++)
        #pragma unroll
        for (int i = 0; i < 4; i++)
            #pragma unroll
            for (int j = 0; j < 4; j++)
                #pragma unroll
                for (int q = 0; q < 4; q++) acc[b][i][j][q] = 0.0f;

    auto fetchA = [&](int kc, float4 pf[8]) {
        int row = tid >> 1;
        const float* bp;
        int sec = kc >> 1;
        if (sec == 0)      bp = nodes + (size_t)sidx[row] * D;
        else if (sec == 1) bp = nodes + (size_t)ridx[row] * D;
        else { int e = e0 + row; int ec = e < E ? e : E - 1; bp = edges + (size_t)ec * D; }
        bp += (kc & 1) * 64;
        const float4* p4 = (const float4*)bp + (tid & 1) * 8;
        #pragma unroll
        for (int i = 0; i < 8; i++) pf[i] = p4[i];
    };
    auto storeA = [&](int stage, const float4 pf[8]) {
        int row = tid >> 1;
        char* A = smem + (stage * 3) * TILE_B;
        #pragma unroll
        for (int i = 0; i < 8; i++) {
            float4 x = pf[i];
            uint32_t h0 = pack_f16(x.x, x.y);
            uint32_t h1 = pack_f16(x.z, x.w);
            uint32_t off = row * ROWSTRIDE + ((tid & 1) * 8 + i) * 8;
            *(uint2*)(A + off) = make_uint2(h0, h1);
        }
    };
    auto cpasyncW0 = [&](int kc, int stage) {
        const char* gp[2] = {(const char*)g_W0T[0], (const char*)g_W0T[1]};
        #pragma unroll
        for (int u = 0; u < 8; u++) {
            int i = tid + u * 256;
            int t = i >> 10, r = i & 1023, n = r >> 3, q = r & 7;
            cp_async16(sb + (stage * 3 + 1 + t) * TILE_B + n * ROWSTRIDE + q * 16,
                       gp[t] + n * 768 + kc * 128 + q * 16);
        }
    };
    auto cpasyncW1_once = [&]() {
        #pragma unroll
        for (int u = 0; u < 16; u++) {
            int i = tid + u * 256;
            int t = i >> 10;                 // 0..3 -> tiles 6..9
            int br = t >> 1, c = t & 1;
            int r = i & 1023, n = r >> 3, q = r & 7;
            cp_async16(sb + (6 + t) * TILE_B + n * ROWSTRIDE + q * 16,
                       (const char*)g_W1T[br] + n * 256 + c * 128 + q * 16);
        }
    };
    // layer-1 MMA: both branches, single pass
    auto mma_2br = [&](int base) {
        uint32_t A = sb + base * TILE_B;
        #pragma unroll
        for (int kk = 0; kk < 4; kk++) {
            uint32_t ah[4][4];
            #pragma unroll
            for (int i = 0; i < 4; i++) {
                uint32_t off = (wm * 64 + i * 16 + (lane & 15)) * ROWSTRIDE
                             + (lane >> 4) * 16 + kk * 32;
                ldsm_x4(A + off, ah[i]);
            }
            #pragma unroll
            for (int br = 0; br < 2; br++) {
                uint32_t W = sb + (base + 1 + br) * TILE_B;
                uint32_t boffA = (wn * 32 + ((lane >> 4) * 8) + (lane & 7)) * ROWSTRIDE
                               + ((lane >> 3) & 1) * 16 + kk * 32;
                uint32_t boffB = boffA + 16 * ROWSTRIDE;
                uint32_t bh[2][4];
                ldsm_x4(W + boffA, bh[0]);
                ldsm_x4(W + boffB, bh[1]);
                #pragma unroll
                for (int i = 0; i < 4; i++)
                    #pragma unroll
                    for (int j = 0; j < 4; j++)
                        mma_f16(acc[br][i][j], ah[i], bh[j >> 1][(j & 1) * 2], bh[j >> 1][(j & 1) * 2 + 1]);
            }
        }
    };
    // layer-2 MMA: one branch, one 64-k chunk, single pass
    auto mma_1br = [&](int br, int tH, int tW) {
        uint32_t A = sb + tH * TILE_B;
        uint32_t W = sb + tW * TILE_B;
        #pragma unroll
        for (int kk = 0; kk < 4; kk++) {
            uint32_t ah[4][4];
            #pragma unroll
            for (int i = 0; i < 4; i++) {
                uint32_t off = (wm * 64 + i * 16 + (lane & 15)) * ROWSTRIDE
                             + (lane >> 4) * 16 + kk * 32;
                ldsm_x4(A + off, ah[i]);
            }
            uint32_t boffA = (wn * 32 + ((lane >> 4) * 8) + (lane & 7)) * ROWSTRIDE
                           + ((lane >> 3) & 1) * 16 + kk * 32;
            uint32_t boffB = boffA + 16 * ROWSTRIDE;
            uint32_t bh[2][4];
            ldsm_x4(W + boffA, bh[0]);
            ldsm_x4(W + boffB, bh[1]);
            #pragma unroll
            for (int i = 0; i < 4; i++)
                #pragma unroll
                for (int j = 0; j < 4; j++)
                    mma_f16(acc[br][i][j], ah[i], bh[j >> 1][(j & 1) * 2], bh[j >> 1][(j & 1) * 2 + 1]);
        }
    };

    // ---------------- layer 1: 6 K-chunks, double-buffered ----------------
    {
        float4 pf[8];
        fetchA(0, pf);
        cpasyncW1_once();               // tiles 6-9, live until layer 2
        cpasyncW0(0, 0);
        CP_COMMIT();
        storeA(0, pf);
        CP_WAIT0();
        __syncthreads();

        #pragma unroll 1
        for (int kc = 0; kc < 6; kc++) {
            int stage = kc & 1;
            if (kc < 5) {
                fetchA(kc + 1, pf);
                cpasyncW0(kc + 1, stage ^ 1);
                CP_COMMIT();
            }
            mma_2br(stage * 3);
            if (kc < 5) {
                storeA(stage ^ 1, pf);
                CP_WAIT0();
            }
            __syncthreads();
        }
    }

    // ---------------- epilogue 1: H = f16(leaky(acc + b0)) -----------------
    {
        const int chunk = wn >> 1;
        #pragma unroll
        for (int br = 0; br < 2; br++) {
            int th = (br ? 2 : 0) + chunk;
            char* Hh = smem + th * TILE_B;
            const float* b0p = bias + br * 256;
            #pragma unroll
            for (int i = 0; i < 4; i++) {
                int r0 = wm * 64 + i * 16 + (lane >> 2);
                #pragma unroll
                for (int j = 0; j < 4; j++) {
                    int c  = wn * 32 + j * 8 + (lane & 3) * 2;
                    int cl = c & 63;
                    float2 bb = *(const float2*)(b0p + c);
                    float v0 = leaky(acc[br][i][j][0] + bb.x);
                    float v1 = leaky(acc[br][i][j][1] + bb.y);
                    float v2 = leaky(acc[br][i][j][2] + bb.x);
                    float v3 = leaky(acc[br][i][j][3] + bb.y);
                    *(uint32_t*)(Hh + r0 * ROWSTRIDE + cl * 2) = pack_f16(v0, v1);
                    *(uint32_t*)(Hh + (r0 + 8) * ROWSTRIDE + cl * 2) = pack_f16(v2, v3);
                }
            }
        }
    }
    __syncthreads();

    // ---------------- layer 2 branch 0 (node messages) ---------------------
    #pragma unroll
    for (int i = 0; i < 4; i++)
        #pragma unroll
        for (int j = 0; j < 4; j++)
            #pragma unroll
            for (int q = 0; q < 4; q++) acc[0][i][j][q] = 0.0f;
    mma_1br(0, 0, 6);
    mma_1br(0, 1, 7);
    __syncthreads();

    // ---------------- stage node-out; TMA-reduce scatter --------------------
    {
        // wm=0 rows 0-63 -> tiles 0-1 region; wm=1 rows 64-127 -> tiles 6-7
        char* stag = smem + (wm ? 6 * TILE_B : 0);
        const float* b1p = bias + 128;
        #pragma unroll
        for (int i = 0; i < 4; i++) {
            int r0 = wm * 64 + i * 16 + (lane >> 2);
            int rl = r0 & 63;
            #pragma unroll
            for (int j = 0; j < 4; j++) {
                int c = wn * 32 + j * 8 + (lane & 3) * 2;
                float2 bb = *(const float2*)(b1p + c);
                *(float2*)(stag + rl * STAG_STRIDE + c * 4) =
                    make_float2(leaky(acc[0][i][j][0] + bb.x), leaky(acc[0][i][j][1] + bb.y));
                *(float2*)(stag + (rl + 8) * STAG_STRIDE + c * 4) =
                    make_float2(leaky(acc[0][i][j][2] + bb.x), leaky(acc[0][i][j][3] + bb.y));
            }
        }
    }
    __syncthreads();
    FENCE_PROXY_ASYNC();
    if (tid < 128 && (e0 + tid) < E) {
        const float* dst = new_nodes + (size_t)ridx[tid] * D;
        uint32_t src = (tid < 64) ? (sb + tid * STAG_STRIDE)
                                  : (sb + 6 * TILE_B + (tid - 64) * STAG_STRIDE);
        asm volatile("cp.reduce.async.bulk.global.shared::cta.bulk_group.add.f32 [%0], [%1], %2;"
                     :: "l"(dst), "r"(src), "r"(512) : "memory");
    }
    asm volatile("cp.async.bulk.commit_group;" ::: "memory");

    // ---------------- layer 2 branch 1 (edge update) ------------------------
    #pragma unroll
    for (int i = 0; i < 4; i++)
        #pragma unroll
        for (int j = 0; j < 4; j++)
            #pragma unroll
            for (int q = 0; q < 4; q++) acc[1][i][j][q] = 0.0f;
    mma_1br(1, 2, 8);
    mma_1br(1, 3, 9);

    {
        const float* b1p = bias + 384;
        #pragma unroll
        for (int i = 0; i < 4; i++) {
            int r0 = wm * 64 + i * 16 + (lane >> 2);
            #pragma unroll
            for (int j = 0; j < 4; j++) {
                int c = wn * 32 + j * 8 + (lane & 3) * 2;
                float2 bb = *(const float2*)(b1p + c);
                int eA = e0 + r0, eB = eA + 8;
                if (eA < E)
                    *(float2*)(new_edges + (size_t)eA * D + c) =
                        make_float2(leaky(acc[1][i][j][0] + bb.x), leaky(acc[1][i][j][1] + bb.y));
                if (eB < E)
                    *(float2*)(new_edges + (size_t)eB * D + c) =
                        make_float2(leaky(acc[1][i][j][2] + bb.x), leaky(acc[1][i][j][3] + bb.y));
            }
        }
    }
    asm volatile("cp.async.bulk.wait_group.read 0;" ::: "memory");
}

// ============================================================================
extern "C" void kernel_launch(void* const* d_in, const int* in_sizes, int n_in,
                              void* d_out, int out_size)
{
    const float* nodes     = (const float*)d_in[0];
    const float* edges     = (const float*)d_in[1];
    const float* globals_  = (const float*)d_in[2];
    const int*   senders   = (const int*)d_in[3];
    const int*   receivers = (const int*)d_in[4];
    const int*   n_node    = (const int*)d_in[5];
    const int*   n_edge    = (const int*)d_in[6];

    const float* node_W0 = (const float*)d_in[7];
    const float* node_b0 = (const float*)d_in[8];
    const float* node_W1 = (const float*)d_in[9];
    const float* node_b1 = (const float*)d_in[10];
    const float* edge_W0 = (const float*)d_in[11];
    const float* edge_b0 = (const float*)d_in[12];
    const float* edge_W1 = (const float*)d_in[13];
    const float* edge_b1 = (const float*)d_in[14];
    const float* glob_W0 = (const float*)d_in[15];
    const float* glob_b0 = (const float*)d_in[16];
    const float* glob_W1 = (const float*)d_in[17];
    const float* glob_b1 = (const float*)d_in[18];
    const float* gnode_W0 = (const float*)d_in[19];
    const float* gnode_b0 = (const float*)d_in[20];
    const float* gnode_W1 = (const float*)d_in[21];
    const float* gnode_b1 = (const float*)d_in[22];
    const float* gedge_W0 = (const float*)d_in[23];
    const float* gedge_b0 = (const float*)d_in[24];
    const float* gedge_W1 = (const float*)d_in[25];
    const float* gedge_b1 = (const float*)d_in[26];
    const float* fin_W0 = (const float*)d_in[27];
    const float* fin_b0 = (const float*)d_in[28];
    const float* fin_W1 = (const float*)d_in[29];
    const float* fin_b1 = (const float*)d_in[30];

    const int N = in_sizes[0] / D;
    const int E = in_sizes[3];
    const int G = in_sizes[5];

    float* new_nodes  = (float*)d_out;
    float* new_edges  = new_nodes + (size_t)N * D;
    float* new_global = new_edges + (size_t)E * D;

    // [0] zero segment-sum target
    int n4 = N * D / 4;
    zero_nodes_kernel<<<(n4 + 255) / 256, 256>>>((float4*)new_nodes, n4);

    // [1] weight prep
    prep_weights<<<512, 256>>>(node_W0, node_W1, edge_W0, edge_W1);

    // [2] per-graph partial sums
    dim3 gs(G, 2, 4);
    graph_sum_kernel<<<gs, 128>>>(nodes, edges, n_node, n_edge, G);

    // [3] global branch MLPs
    dim3 gb(G, 3);
    global_branch_kernel<<<gb, 128>>>(globals_,
        glob_W0, glob_b0, glob_W1, glob_b1,
        gnode_W0, gnode_b0, gnode_W1, gnode_b1,
        gedge_W0, gedge_b0, gedge_W1, gedge_b1);

    // [4] final global MLP
    global_final_kernel<<<G, 128>>>(fin_W0, fin_b0, fin_W1, fin_b1, new_global);

    // [5] main edge kernel
    cudaFuncSetAttribute(edge_mma_kernel,
                         cudaFuncAttributeMaxDynamicSharedMemorySize, SMEM_BYTES);
    int grid = (E + 127) / 128;
    edge_mma_kernel<<<grid, 256, SMEM_BYTES>>>(
        nodes, edges, senders, receivers,
        node_b0, node_b1, edge_b0, edge_b1,
        new_nodes, new_edges, E);
}

// round 7
// speedup vs baseline: 7.7359x; 1.0699x over previous
#include <cuda_runtime.h>
#include <cuda_fp16.h>
#include <cstdint>

#define D 128
#define TILE_B 18432            // one [128 rows][64 fp16 cols] tile, 144B stride
#define ROWSTRIDE 144
#define NTILES 10
#define TILES_BYTES (NTILES * TILE_B)      // 184320
#define IDX_OFF  TILES_BYTES               // sidx[128], ridx[128]
#define BIAS_OFF (IDX_OFF + 1024)          // 512 floats
#define SMEM_BYTES (BIAS_OFF + 2048)       // 187392
#define STAG_STRIDE 528                    // node-out staging row stride (16B aligned)

__device__ __forceinline__ uint32_t smem_u32(const void* p) {
    uint32_t a;
    asm("{ .reg .u64 t; cvta.to.shared.u64 t, %1; cvt.u32.u64 %0, t; }" : "=r"(a) : "l"(p));
    return a;
}
__device__ __forceinline__ float leaky(float x) { return x > 0.0f ? x : 0.01f * x; }
__device__ __forceinline__ uint32_t pack_f16(float a, float b) {
    __half2 t = __floats2half2_rn(a, b);
    return reinterpret_cast<uint32_t&>(t);
}
__device__ __forceinline__ void ldsm_x4(uint32_t addr, uint32_t r[4]) {
    asm volatile("ldmatrix.sync.aligned.m8n8.x4.shared.b16 {%0,%1,%2,%3}, [%4];"
                 : "=r"(r[0]), "=r"(r[1]), "=r"(r[2]), "=r"(r[3]) : "r"(addr));
}
__device__ __forceinline__ void mma_f16(float* c, const uint32_t* a, uint32_t b0, uint32_t b1) {
    asm volatile("mma.sync.aligned.m16n8k16.row.col.f32.f16.f16.f32 "
                 "{%0,%1,%2,%3}, {%4,%5,%6,%7}, {%8,%9}, {%0,%1,%2,%3};"
                 : "+f"(c[0]), "+f"(c[1]), "+f"(c[2]), "+f"(c[3])
                 : "r"(a[0]), "r"(a[1]), "r"(a[2]), "r"(a[3]), "r"(b0), "r"(b1));
}
__device__ __forceinline__ void cp_async16(uint32_t saddr, const void* gaddr) {
    asm volatile("cp.async.cg.shared.global [%0], [%1], 16;" :: "r"(saddr), "l"(gaddr));
}
#define CP_COMMIT()  asm volatile("cp.async.commit_group;" ::: "memory")
#define CP_WAIT0()   asm volatile("cp.async.wait_group 0;" ::: "memory")
#define FENCE_PROXY_ASYNC() asm volatile("fence.proxy.async.shared::cta;" ::: "memory")

// ============================================================================
// Device scratch
// ============================================================================
__device__ __half g_W0T[2][128 * 384];   // [branch][n][k] transposed fp16
__device__ __half g_W1T[2][128 * 128];
__device__ float g_part[2][256][4][128]; // per-graph partial sums
__device__ float g_cat[256][384];        // concat of 3 global-branch MLPs

// ============================================================================
// [0] zero new_nodes
// ============================================================================
__global__ void zero_nodes_kernel(float4* __restrict__ p, int n4) {
    int i = blockIdx.x * 256 + threadIdx.x;
    if (i < n4) p[i] = make_float4(0.f, 0.f, 0.f, 0.f);
}

// ============================================================================
// [1] weight prep: transpose + fp16 convert
// ============================================================================
__global__ void prep_weights(const float* __restrict__ nW0, const float* __restrict__ nW1,
                             const float* __restrict__ eW0, const float* __restrict__ eW1)
{
    int i = blockIdx.x * 256 + threadIdx.x;
    if (i < 98304) {                      // W0T: 2 * 128*384
        int b = i / 49152, r = i % 49152;
        int n = r / 384, k = r % 384;
        g_W0T[b][n * 384 + k] = __float2half_rn((b ? eW0 : nW0)[k * 128 + n]);
    } else if (i < 131072) {              // W1T: 2 * 128*128
        int j = i - 98304;
        int b = j / 16384, r = j % 16384;
        int n = r / 128, k = r % 128;
        g_W1T[b][n * 128 + k] = __float2half_rn((b ? eW1 : nW1)[k * 128 + n]);
    }
}

// ============================================================================
// [2] per-graph segment partial sums: grid (G, 2, 4), block 128
// ============================================================================
__global__ void graph_sum_kernel(const float* __restrict__ nodes,
                                 const float* __restrict__ edges,
                                 const int* __restrict__ n_node,
                                 const int* __restrict__ n_edge, int G)
{
    int g = blockIdx.x, which = blockIdx.y, part = blockIdx.z;
    const float* src = which ? edges : nodes;
    const int*  cnts = which ? n_edge : n_node;

    int start = 0;
    for (int i = 0; i < g; i++) start += cnts[i];
    int cnt = cnts[g];

    int d = threadIdx.x;
    float s0 = 0.f, s1 = 0.f, s2 = 0.f, s3 = 0.f;
    const float* p = src + (size_t)start * D + d;
    int i = part;
    for (; i + 3 * 4 < cnt; i += 16) {
        s0 += p[(size_t)i * D];
        s1 += p[(size_t)(i + 4) * D];
        s2 += p[(size_t)(i + 8) * D];
        s3 += p[(size_t)(i + 12) * D];
    }
    for (; i < cnt; i += 4) s0 += p[(size_t)i * D];
    g_part[which][g][part][d] = s0 + s1 + s2 + s3;
}

// ============================================================================
// [3] global branch MLPs: grid (G, 3), block 128 -> g_cat
// ============================================================================
__global__ void global_branch_kernel(const float* __restrict__ globals_,
                                     const float* gW0, const float* gb0, const float* gW1, const float* gb1,
                                     const float* nW0, const float* nb0, const float* nW1, const float* nb1,
                                     const float* eW0, const float* eb0, const float* eW1, const float* eb1)
{
    __shared__ float in[D];
    __shared__ float h[D];
    int g = blockIdx.x, b = blockIdx.y, d = threadIdx.x;

    const float *W0, *b0, *W1, *b1;
    if (b == 0)      { W0 = gW0; b0 = gb0; W1 = gW1; b1 = gb1;
                       in[d] = globals_[(size_t)g * D + d]; }
    else if (b == 1) { W0 = nW0; b0 = nb0; W1 = nW1; b1 = nb1;
                       in[d] = g_part[0][g][0][d] + g_part[0][g][1][d]
                             + g_part[0][g][2][d] + g_part[0][g][3][d]; }
    else             { W0 = eW0; b0 = eb0; W1 = eW1; b1 = eb1;
                       in[d] = g_part[1][g][0][d] + g_part[1][g][1][d]
                             + g_part[1][g][2][d] + g_part[1][g][3][d]; }
    __syncthreads();

    float a0 = 0.f, a1 = 0.f, a2 = 0.f, a3 = 0.f;
    #pragma unroll 8
    for (int k = 0; k < D; k += 4) {
        a0 = fmaf(in[k],     __ldg(W0 + k * D + d),       a0);
        a1 = fmaf(in[k + 1], __ldg(W0 + (k + 1) * D + d), a1);
        a2 = fmaf(in[k + 2], __ldg(W0 + (k + 2) * D + d), a2);
        a3 = fmaf(in[k + 3], __ldg(W0 + (k + 3) * D + d), a3);
    }
    h[d] = leaky((a0 + a1) + (a2 + a3) + __ldg(b0 + d));
    __syncthreads();

    a0 = a1 = a2 = a3 = 0.f;
    #pragma unroll 8
    for (int k = 0; k < D; k += 4) {
        a0 = fmaf(h[k],     __ldg(W1 + k * D + d),       a0);
        a1 = fmaf(h[k + 1], __ldg(W1 + (k + 1) * D + d), a1);
        a2 = fmaf(h[k + 2], __ldg(W1 + (k + 2) * D + d), a2);
        a3 = fmaf(h[k + 3], __ldg(W1 + (k + 3) * D + d), a3);
    }
    g_cat[g][b * D + d] = leaky((a0 + a1) + (a2 + a3) + __ldg(b1 + d));
}

// ============================================================================
// [4] final global MLP: grid G, block 128
// ============================================================================
__global__ void global_final_kernel(const float* fW0, const float* fb0,
                                    const float* fW1, const float* fb1,
                                    float* __restrict__ out_global)
{
    __shared__ float cat[3 * D];
    __shared__ float h[D];
    int g = blockIdx.x, d = threadIdx.x;
    cat[d]         = g_cat[g][d];
    cat[D + d]     = g_cat[g][D + d];
    cat[2 * D + d] = g_cat[g][2 * D + d];
    __syncthreads();

    float a0 = 0.f, a1 = 0.f, a2 = 0.f, a3 = 0.f;
    #pragma unroll 8
    for (int k = 0; k < 3 * D; k += 4) {
        a0 = fmaf(cat[k],     __ldg(fW0 + k * D + d),       a0);
        a1 = fmaf(cat[k + 1], __ldg(fW0 + (k + 1) * D + d), a1);
        a2 = fmaf(cat[k + 2], __ldg(fW0 + (k + 2) * D + d), a2);
        a3 = fmaf(cat[k + 3], __ldg(fW0 + (k + 3) * D + d), a3);
    }
    h[d] = leaky((a0 + a1) + (a2 + a3) + __ldg(fb0 + d));
    __syncthreads();

    a0 = a1 = a2 = a3 = 0.f;
    #pragma unroll 8
    for (int k = 0; k < D; k += 4) {
        a0 = fmaf(h[k],     __ldg(fW1 + k * D + d),       a0);
        a1 = fmaf(h[k + 1], __ldg(fW1 + (k + 1) * D + d), a1);
        a2 = fmaf(h[k + 2], __ldg(fW1 + (k + 2) * D + d), a2);
        a3 = fmaf(h[k + 3], __ldg(fW1 + (k + 3) * D + d), a3);
    }
    out_global[(size_t)g * D + d] = leaky((a0 + a1) + (a2 + a3) + __ldg(fb1 + d));
}

// ============================================================================
// [5] main fused edge kernel: pure fp16 mma.sync, 512 threads / 16 warps
// Warp tile 32(M) x 32(N): wm = wid>>2 (0..3), wn = wid&3 (0..3)
// Tile map (10 tiles):
//   layer1 stage s: s*3 + {0:A, 1:Wn, 2:We}        (tiles 0-5)
//   W1 preloaded:   6:Wn1_c0, 7:Wn1_c1, 8:We1_c0, 9:We1_c1
//   layer2 H: node c0->0, c1->1 ; edge c0->2, c1->3
//   node-out staging: rows 0-63 -> tiles 0-1 ; rows 64-127 -> tiles 6-7
// ============================================================================
__global__ __launch_bounds__(512, 1)
void edge_mma_kernel(const float* __restrict__ nodes,
                     const float* __restrict__ edges,
                     const int*   __restrict__ senders,
                     const int*   __restrict__ receivers,
                     const float* __restrict__ nb0f, const float* __restrict__ nb1f,
                     const float* __restrict__ eb0f, const float* __restrict__ eb1f,
                     float* __restrict__ new_nodes,
                     float* __restrict__ new_edges,
                     int E)
{
    extern __shared__ char smem[];
    const uint32_t sb = smem_u32(smem);
    const int tid  = threadIdx.x;
    const int wid  = tid >> 5;
    const int lane = tid & 31;
    const int wm   = wid >> 2;        // 0..3  (M offset wm*32)
    const int wn   = wid & 3;         // 0..3  (N offset wn*32)
    const int e0   = blockIdx.x * 128;

    int*   sidx = (int*)(smem + IDX_OFF);
    int*   ridx = (int*)(smem + IDX_OFF + 512);
    float* bias = (float*)(smem + BIAS_OFF);

    if (tid < 128) {
        int e  = e0 + tid;
        int ec = e < E ? e : E - 1;
        sidx[tid] = senders[ec];
        ridx[tid] = receivers[ec];
        bias[tid]       = nb0f[tid];
        bias[128 + tid] = nb1f[tid];
        bias[256 + tid] = eb0f[tid];
        bias[384 + tid] = eb1f[tid];
    }
    __syncthreads();

    // acc[branch][i(2 x m16)][j(4 x n8)][quad]
    float acc[2][2][4][4];
    #pragma unroll
    for (int b = 0; b < 2; b++)
        #pragma unroll
        for (int i = 0; i < 2; i++)
            #pragma unroll
            for (int j = 0; j < 4; j++)
                #pragma unroll
                for (int q = 0; q < 4; q++) acc[b][i][j][q] = 0.0f;

    auto fetchA = [&](int kc, float4 pf[4]) {
        int row = tid >> 2;
        const float* bp;
        int sec = kc >> 1;
        if (sec == 0)      bp = nodes + (size_t)sidx[row] * D;
        else if (sec == 1) bp = nodes + (size_t)ridx[row] * D;
        else { int e = e0 + row; int ec = e < E ? e : E - 1; bp = edges + (size_t)ec * D; }
        bp += (kc & 1) * 64;
        const float4* p4 = (const float4*)bp + (tid & 3) * 4;
        #pragma unroll
        for (int i = 0; i < 4; i++) pf[i] = p4[i];
    };
    auto storeA = [&](int stage, const float4 pf[4]) {
        int row = tid >> 2;
        char* A = smem + (stage * 3) * TILE_B;
        #pragma unroll
        for (int i = 0; i < 4; i++) {
            float4 x = pf[i];
            uint32_t h0 = pack_f16(x.x, x.y);
            uint32_t h1 = pack_f16(x.z, x.w);
            uint32_t off = row * ROWSTRIDE + ((tid & 3) * 4 + i) * 8;
            *(uint2*)(A + off) = make_uint2(h0, h1);
        }
    };
    auto cpasyncW0 = [&](int kc, int stage) {
        const char* gp[2] = {(const char*)g_W0T[0], (const char*)g_W0T[1]};
        #pragma unroll
        for (int u = 0; u < 4; u++) {
            int i = tid + u * 512;
            int t = i >> 10, r = i & 1023, n = r >> 3, q = r & 7;
            cp_async16(sb + (stage * 3 + 1 + t) * TILE_B + n * ROWSTRIDE + q * 16,
                       gp[t] + n * 768 + kc * 128 + q * 16);
        }
    };
    auto cpasyncW1_once = [&]() {
        #pragma unroll
        for (int u = 0; u < 8; u++) {
            int i = tid + u * 512;
            int t = i >> 10;                 // 0..3 -> tiles 6..9
            int br = t >> 1, c = t & 1;
            int r = i & 1023, n = r >> 3, q = r & 7;
            cp_async16(sb + (6 + t) * TILE_B + n * ROWSTRIDE + q * 16,
                       (const char*)g_W1T[br] + n * 256 + c * 128 + q * 16);
        }
    };
    // layer-1 MMA: both branches
    auto mma_2br = [&](int base) {
        uint32_t A = sb + base * TILE_B;
        #pragma unroll
        for (int kk = 0; kk < 4; kk++) {
            uint32_t ah[2][4];
            #pragma unroll
            for (int i = 0; i < 2; i++) {
                uint32_t off = (wm * 32 + i * 16 + (lane & 15)) * ROWSTRIDE
                             + (lane >> 4) * 16 + kk * 32;
                ldsm_x4(A + off, ah[i]);
            }
            #pragma unroll
            for (int br = 0; br < 2; br++) {
                uint32_t W = sb + (base + 1 + br) * TILE_B;
                uint32_t boffA = (wn * 32 + ((lane >> 4) * 8) + (lane & 7)) * ROWSTRIDE
                               + ((lane >> 3) & 1) * 16 + kk * 32;
                uint32_t boffB = boffA + 16 * ROWSTRIDE;
                uint32_t bh[2][4];
                ldsm_x4(W + boffA, bh[0]);
                ldsm_x4(W + boffB, bh[1]);
                #pragma unroll
                for (int i = 0; i < 2; i++)
                    #pragma unroll
                    for (int j = 0; j < 4; j++)
                        mma_f16(acc[br][i][j], ah[i], bh[j >> 1][(j & 1) * 2], bh[j >> 1][(j & 1) * 2 + 1]);
            }
        }
    };
    // layer-2 MMA: one branch, one 64-k chunk
    auto mma_1br = [&](int br, int tH, int tW) {
        uint32_t A = sb + tH * TILE_B;
        uint32_t W = sb + tW * TILE_B;
        #pragma unroll
        for (int kk = 0; kk < 4; kk++) {
            uint32_t ah[2][4];
            #pragma unroll
            for (int i = 0; i < 2; i++) {
                uint32_t off = (wm * 32 + i * 16 + (lane & 15)) * ROWSTRIDE
                             + (lane >> 4) * 16 + kk * 32;
                ldsm_x4(A + off, ah[i]);
            }
            uint32_t boffA = (wn * 32 + ((lane >> 4) * 8) + (lane & 7)) * ROWSTRIDE
                           + ((lane >> 3) & 1) * 16 + kk * 32;
            uint32_t boffB = boffA + 16 * ROWSTRIDE;
            uint32_t bh[2][4];
            ldsm_x4(W + boffA, bh[0]);
            ldsm_x4(W + boffB, bh[1]);
            #pragma unroll
            for (int i = 0; i < 2; i++)
                #pragma unroll
                for (int j = 0; j < 4; j++)
                    mma_f16(acc[br][i][j], ah[i], bh[j >> 1][(j & 1) * 2], bh[j >> 1][(j & 1) * 2 + 1]);
        }
    };

    // ---------------- layer 1: 6 K-chunks, double-buffered ----------------
    {
        float4 pf[4];
        fetchA(0, pf);
        cpasyncW1_once();               // tiles 6-9, live until layer 2
        cpasyncW0(0, 0);
        CP_COMMIT();
        storeA(0, pf);
        CP_WAIT0();
        __syncthreads();

        #pragma unroll 1
        for (int kc = 0; kc < 6; kc++) {
            int stage = kc & 1;
            if (kc < 5) {
                fetchA(kc + 1, pf);
                cpasyncW0(kc + 1, stage ^ 1);
                CP_COMMIT();
            }
            mma_2br(stage * 3);
            if (kc < 5) {
                storeA(stage ^ 1, pf);
                CP_WAIT0();
            }
            __syncthreads();
        }
    }

    // ---------------- epilogue 1: H = f16(leaky(acc + b0)) -----------------
    {
        const int chunk = wn >> 1;
        #pragma unroll
        for (int br = 0; br < 2; br++) {
            int th = (br ? 2 : 0) + chunk;
            char* Hh = smem + th * TILE_B;
            const float* b0p = bias + br * 256;
            #pragma unroll
            for (int i = 0; i < 2; i++) {
                int r0 = wm * 32 + i * 16 + (lane >> 2);
                #pragma unroll
                for (int j = 0; j < 4; j++) {
                    int c  = wn * 32 + j * 8 + (lane & 3) * 2;
                    int cl = c & 63;
                    float2 bb = *(const float2*)(b0p + c);
                    float v0 = leaky(acc[br][i][j][0] + bb.x);
                    float v1 = leaky(acc[br][i][j][1] + bb.y);
                    float v2 = leaky(acc[br][i][j][2] + bb.x);
                    float v3 = leaky(acc[br][i][j][3] + bb.y);
                    *(uint32_t*)(Hh + r0 * ROWSTRIDE + cl * 2) = pack_f16(v0, v1);
                    *(uint32_t*)(Hh + (r0 + 8) * ROWSTRIDE + cl * 2) = pack_f16(v2, v3);
                }
            }
        }
    }
    __syncthreads();

    // ---------------- layer 2 branch 0 (node messages) ---------------------
    #pragma unroll
    for (int i = 0; i < 2; i++)
        #pragma unroll
        for (int j = 0; j < 4; j++)
            #pragma unroll
            for (int q = 0; q < 4; q++) acc[0][i][j][q] = 0.0f;
    mma_1br(0, 0, 6);
    mma_1br(0, 1, 7);
    __syncthreads();

    // ---------------- stage node-out; TMA-reduce scatter --------------------
    {
        // rows 0-63 (wm 0-1) -> tiles 0-1 region; rows 64-127 (wm 2-3) -> tiles 6-7
        char* stag = smem + (wm >= 2 ? 6 * TILE_B : 0);
        const float* b1p = bias + 128;
        #pragma unroll
        for (int i = 0; i < 2; i++) {
            int r0 = wm * 32 + i * 16 + (lane >> 2);
            int rl = r0 & 63;
            #pragma unroll
            for (int j = 0; j < 4; j++) {
                int c = wn * 32 + j * 8 + (lane & 3) * 2;
                float2 bb = *(const float2*)(b1p + c);
                *(float2*)(stag + rl * STAG_STRIDE + c * 4) =
                    make_float2(leaky(acc[0][i][j][0] + bb.x), leaky(acc[0][i][j][1] + bb.y));
                *(float2*)(stag + (rl + 8) * STAG_STRIDE + c * 4) =
                    make_float2(leaky(acc[0][i][j][2] + bb.x), leaky(acc[0][i][j][3] + bb.y));
            }
        }
    }
    __syncthreads();
    FENCE_PROXY_ASYNC();
    if (tid < 128 && (e0 + tid) < E) {
        const float* dst = new_nodes + (size_t)ridx[tid] * D;
        uint32_t src = (tid < 64) ? (sb + tid * STAG_STRIDE)
                                  : (sb + 6 * TILE_B + (tid - 64) * STAG_STRIDE);
        asm volatile("cp.reduce.async.bulk.global.shared::cta.bulk_group.add.f32 [%0], [%1], %2;"
                     :: "l"(dst), "r"(src), "r"(512) : "memory");
    }
    asm volatile("cp.async.bulk.commit_group;" ::: "memory");

    // ---------------- layer 2 branch 1 (edge update) ------------------------
    #pragma unroll
    for (int i = 0; i < 2; i++)
        #pragma unroll
        for (int j = 0; j < 4; j++)
            #pragma unroll
            for (int q = 0; q < 4; q++) acc[1][i][j][q] = 0.0f;
    mma_1br(1, 2, 8);
    mma_1br(1, 3, 9);

    {
        const float* b1p = bias + 384;
        #pragma unroll
        for (int i = 0; i < 2; i++) {
            int r0 = wm * 32 + i * 16 + (lane >> 2);
            #pragma unroll
            for (int j = 0; j < 4; j++) {
                int c = wn * 32 + j * 8 + (lane & 3) * 2;
                float2 bb = *(const float2*)(b1p + c);
                int eA = e0 + r0, eB = eA + 8;
                if (eA < E)
                    *(float2*)(new_edges + (size_t)eA * D + c) =
                        make_float2(leaky(acc[1][i][j][0] + bb.x), leaky(acc[1][i][j][1] + bb.y));
                if (eB < E)
                    *(float2*)(new_edges + (size_t)eB * D + c) =
                        make_float2(leaky(acc[1][i][j][2] + bb.x), leaky(acc[1][i][j][3] + bb.y));
            }
        }
    }
    asm volatile("cp.async.bulk.wait_group.read 0;" ::: "memory");
}

// ============================================================================
extern "C" void kernel_launch(void* const* d_in, const int* in_sizes, int n_in,
                              void* d_out, int out_size)
{
    const float* nodes     = (const float*)d_in[0];
    const float* edges     = (const float*)d_in[1];
    const float* globals_  = (const float*)d_in[2];
    const int*   senders   = (const int*)d_in[3];
    const int*   receivers = (const int*)d_in[4];
    const int*   n_node    = (const int*)d_in[5];
    const int*   n_edge    = (const int*)d_in[6];

    const float* node_W0 = (const float*)d_in[7];
    const float* node_b0 = (const float*)d_in[8];
    const float* node_W1 = (const float*)d_in[9];
    const float* node_b1 = (const float*)d_in[10];
    const float* edge_W0 = (const float*)d_in[11];
    const float* edge_b0 = (const float*)d_in[12];
    const float* edge_W1 = (const float*)d_in[13];
    const float* edge_b1 = (const float*)d_in[14];
    const float* glob_W0 = (const float*)d_in[15];
    const float* glob_b0 = (const float*)d_in[16];
    const float* glob_W1 = (const float*)d_in[17];
    const float* glob_b1 = (const float*)d_in[18];
    const float* gnode_W0 = (const float*)d_in[19];
    const float* gnode_b0 = (const float*)d_in[20];
    const float* gnode_W1 = (const float*)d_in[21];
    const float* gnode_b1 = (const float*)d_in[22];
    const float* gedge_W0 = (const float*)d_in[23];
    const float* gedge_b0 = (const float*)d_in[24];
    const float* gedge_W1 = (const float*)d_in[25];
    const float* gedge_b1 = (const float*)d_in[26];
    const float* fin_W0 = (const float*)d_in[27];
    const float* fin_b0 = (const float*)d_in[28];
    const float* fin_W1 = (const float*)d_in[29];
    const float* fin_b1 = (const float*)d_in[30];

    const int N = in_sizes[0] / D;
    const int E = in_sizes[3];
    const int G = in_sizes[5];

    float* new_nodes  = (float*)d_out;
    float* new_edges  = new_nodes + (size_t)N * D;
    float* new_global = new_edges + (size_t)E * D;

    // [0] zero segment-sum target
    int n4 = N * D / 4;
    zero_nodes_kernel<<<(n4 + 255) / 256, 256>>>((float4*)new_nodes, n4);

    // [1] weight prep
    prep_weights<<<512, 256>>>(node_W0, node_W1, edge_W0, edge_W1);

    // [2] per-graph partial sums
    dim3 gs(G, 2, 4);
    graph_sum_kernel<<<gs, 128>>>(nodes, edges, n_node, n_edge, G);

    // [3] global branch MLPs
    dim3 gb(G, 3);
    global_branch_kernel<<<gb, 128>>>(globals_,
        glob_W0, glob_b0, glob_W1, glob_b1,
        gnode_W0, gnode_b0, gnode_W1, gnode_b1,
        gedge_W0, gedge_b0, gedge_W1, gedge_b1);

    // [4] final global MLP
    global_final_kernel<<<G, 128>>>(fin_W0, fin_b0, fin_W1, fin_b1, new_global);

    // [5] main edge kernel
    cudaFuncSetAttribute(edge_mma_kernel,
                         cudaFuncAttributeMaxDynamicSharedMemorySize, SMEM_BYTES);
    int grid = (E + 127) / 128;
    edge_mma_kernel<<<grid, 512, SMEM_BYTES>>>(
        nodes, edges, senders, receivers,
        node_b0, node_b1, edge_b0, edge_b1,
        new_nodes, new_edges, E);
}